// round 10
// baseline (speedup 1.0000x reference)
#include <cuda_runtime.h>
#include <cuda_bf16.h>
#include <cstdint>
#include <math.h>

#define B_      32
#define S_      2048
#define ENC_    1024
#define DEC_    512
#define WROW    1536
#define M_TOTAL 65536

#define BM 128
#define BN 128
#define KCB 128              // K bytes per stage (int8) = 128 k-values
#define NSTAGE 8
#define NBUF 3
#define NTHREADS 512

// smem layout (from 1024-aligned base)
#define OFF_VS    0
#define OFF_HS    512
#define OFF_SS    1024
#define OFF_TS    1536
#define OFF_RED   2048
#define OFF_TILES 4096
#define STAGE_BYTES 65536    // AQ1 16K | AQ2 16K | BQ1 16K | BQ2 16K
#define SMEM_DYN (1024 + OFF_TILES + NBUF * STAGE_BYTES)   // 201728

__device__ __align__(256) int8_t g_aq1[(size_t)M_TOTAL * ENC_];
__device__ __align__(256) int8_t g_aq2[(size_t)M_TOTAL * ENC_];
__device__ __align__(256) int8_t g_wq1[DEC_ * ENC_];
__device__ __align__(256) int8_t g_wq2[DEC_ * ENC_];
__device__ float g_s1[M_TOTAL];
__device__ float g_t1[DEC_];
__device__ float g_hproj[B_ * DEC_];
__device__ float g_partial[4 * M_TOTAL];

// ---------------- helpers ----------------
__device__ __forceinline__ uint32_t smem_u32(const void* p) {
    uint32_t a;
    asm("{ .reg .u64 t; cvta.to.shared.u64 t, %1; cvt.u32.u64 %0, t; }" : "=r"(a) : "l"(p));
    return a;
}
__device__ __forceinline__ uint32_t swz(uint32_t o) { return o ^ ((o >> 3) & 0x70); }
__device__ __forceinline__ void cp16(uint32_t dst, const void* src) {
    asm volatile("cp.async.cg.shared.global [%0], [%1], 16;"
                 :: "r"(dst), "l"(__cvta_generic_to_global(src)) : "memory");
}
__device__ __forceinline__ float tanh_ffma(float x) {
    float xc = fminf(fmaxf(x, -8.f), 8.f);
    float y  = xc * 2.88539008177793f;
    float t  = y + 12582912.f;
    int   k  = __float_as_int(t) - __float_as_int(12582912.f);
    float f  = y - (t - 12582912.f);
    float p = 1.3333558146e-3f;
    p = fmaf(p, f, 9.6181291076e-3f);
    p = fmaf(p, f, 5.5504108664e-2f);
    p = fmaf(p, f, 2.4022650696e-1f);
    p = fmaf(p, f, 6.9314718056e-1f);
    p = fmaf(p, f, 1.0f);
    float E = __int_as_float(__float_as_int(p) + (k << 23));
    float D = E + 1.f;
    float r = __int_as_float(0x7EF311C3 - __float_as_int(D));
    r = r * fmaf(-D, r, 2.f);
    r = r * fmaf(-D, r, 2.f);
    r = r * fmaf(-D, r, 2.f);
    return fmaf(-2.f, r, 1.f);
}
__device__ __forceinline__ void ldsm4(uint32_t* r, uint32_t addr) {
    asm volatile("ldmatrix.sync.aligned.m8n8.x4.shared.b16 {%0,%1,%2,%3}, [%4];"
                 : "=r"(r[0]), "=r"(r[1]), "=r"(r[2]), "=r"(r[3]) : "r"(addr));
}
__device__ __forceinline__ void imma16832(int* c, const uint32_t* a, uint32_t b0, uint32_t b1) {
    asm volatile("mma.sync.aligned.m16n8k32.row.col.s32.s8.s8.s32 "
                 "{%0,%1,%2,%3}, {%4,%5,%6,%7}, {%8,%9}, {%0,%1,%2,%3};"
                 : "+r"(c[0]), "+r"(c[1]), "+r"(c[2]), "+r"(c[3])
                 : "r"(a[0]), "r"(a[1]), "r"(a[2]), "r"(a[3]), "r"(b0), "r"(b1));
}

// ---------------- two-level int8 quantization of one row (1024 elems, 128 thr) ----
__device__ __forceinline__ void quant_row(const float* __restrict__ src,
                                          int8_t* __restrict__ q1p,
                                          int8_t* __restrict__ q2p,
                                          float* __restrict__ s1p,
                                          int row_elems_stride_unused) {
    __shared__ float wmax[4];
    const int t = threadIdx.x;             // 0..127, 8 elems each
    float4 x0 = *reinterpret_cast<const float4*>(src + t * 8);
    float4 x1 = *reinterpret_cast<const float4*>(src + t * 8 + 4);
    float x[8] = {x0.x, x0.y, x0.z, x0.w, x1.x, x1.y, x1.z, x1.w};
    float m = 0.f;
#pragma unroll
    for (int i = 0; i < 8; i++) m = fmaxf(m, fabsf(x[i]));
#pragma unroll
    for (int o = 16; o > 0; o >>= 1) m = fmaxf(m, __shfl_xor_sync(0xffffffffu, m, o));
    if ((t & 31) == 0) wmax[t >> 5] = m;
    __syncthreads();
    m = fmaxf(fmaxf(wmax[0], wmax[1]), fmaxf(wmax[2], wmax[3]));
    m = fmaxf(m, 1e-20f);
    const float s1  = m * (1.f / 127.f);
    const float is1 = 127.f / m;
    const float is2 = is1 * 254.f;
    if (t == 0) *s1p = s1;
    uint32_t w1[2], w2[2];
#pragma unroll
    for (int h = 0; h < 2; h++) {
        uint32_t a1 = 0, a2 = 0;
#pragma unroll
        for (int j = 0; j < 4; j++) {
            float xv = x[h * 4 + j];
            int q1 = __float2int_rn(xv * is1);
            q1 = max(-127, min(127, q1));
            float r = fmaf((float)(-q1), s1, xv);
            int q2 = __float2int_rn(r * is2);
            q2 = max(-127, min(127, q2));
            a1 |= ((uint32_t)(uint8_t)(int8_t)q1) << (j * 8);
            a2 |= ((uint32_t)(uint8_t)(int8_t)q2) << (j * 8);
        }
        w1[h] = a1; w2[h] = a2;
    }
    *reinterpret_cast<uint2*>(q1p + t * 8) = make_uint2(w1[0], w1[1]);
    *reinterpret_cast<uint2*>(q2p + t * 8) = make_uint2(w2[0], w2[1]);
}

__global__ void quant_a_kernel(const float* __restrict__ enc) {
    const size_t row = blockIdx.x;
    quant_row(enc + row * ENC_, g_aq1 + row * ENC_, g_aq2 + row * ENC_, g_s1 + row, 0);
}
__global__ void quant_we_kernel(const float* __restrict__ W) {
    const size_t d = blockIdx.x;
    quant_row(W + d * WROW + DEC_, g_wq1 + d * ENC_, g_wq2 + d * ENC_, g_t1 + d, 0);
}

// ---------------- hproj ----------------
__global__ void hproj_kernel(const float* __restrict__ hidden,
                             const float* __restrict__ W,
                             const float* __restrict__ bvec) {
    __shared__ float hid[DEC_];
    const int b = blockIdx.y;
    const int n = blockIdx.x * 128 + threadIdx.x;
    for (int i = threadIdx.x; i < DEC_; i += 128) hid[i] = hidden[b * DEC_ + i];
    __syncthreads();
    const float4* wr = reinterpret_cast<const float4*>(W + (size_t)n * WROW);
    float acc = bvec[n];
#pragma unroll 8
    for (int k = 0; k < DEC_ / 4; k++) {
        float4 w = wr[k];
        acc += hid[k*4]*w.x + hid[k*4+1]*w.y + hid[k*4+2]*w.z + hid[k*4+3]*w.w;
    }
    g_hproj[b * DEC_ + n] = acc;
}

// ---------------- IMMA GEMM + fused epilogue ----------------
__global__ __launch_bounds__(NTHREADS, 1)
void gemm_kernel(const float* __restrict__ v) {
    extern __shared__ char sraw[];
    uint32_t sb0 = smem_u32(sraw);
    uint32_t sb = (sb0 + 1023u) & ~1023u;
    char* smem = sraw + (sb - sb0);

    const int tid  = threadIdx.x;
    const int lane = tid & 31;
    const int w    = tid >> 5;           // 0..15
    const int wm   = w >> 2;             // 0..3 (M: 32 rows)
    const int wn   = w & 3;              // 0..3 (N: 32 cols)
    const int g8   = lane >> 3;
    const int r8   = lane & 7;
    const int n0   = blockIdx.x * BN;
    const int m0   = blockIdx.y * BM;
    const int batch = m0 >> 11;

    float* vs = (float*)(smem + OFF_VS);
    float* hs = (float*)(smem + OFF_HS);
    float* ss = (float*)(smem + OFF_SS);
    float* ts = (float*)(smem + OFF_TS);
    if (tid < 128) {
        vs[tid] = v[n0 + tid];
        hs[tid] = g_hproj[batch * DEC_ + n0 + tid];
        ss[tid] = g_s1[m0 + tid];
        ts[tid] = g_t1[n0 + tid];
    }

    // prologue: stages 0,1
#pragma unroll
    for (int s = 0; s < 2; s++) {
        uint32_t ab = sb + OFF_TILES + s * STAGE_BYTES;
        const int kb = s * KCB;
#pragma unroll
        for (int i = 0; i < 2; i++) {
            int id = tid + i * NTHREADS;
            int row = id >> 3, c = id & 7;
            uint32_t so = swz(row * 128 + c * 16);
            size_t ga = (size_t)(m0 + row) * ENC_ + kb + c * 16;
            size_t gb = (size_t)(n0 + row) * ENC_ + kb + c * 16;
            cp16(ab + so,         g_aq1 + ga);
            cp16(ab + 16384 + so, g_aq2 + ga);
            cp16(ab + 32768 + so, g_wq1 + gb);
            cp16(ab + 49152 + so, g_wq2 + gb);
        }
        asm volatile("cp.async.commit_group;" ::: "memory");
    }

    int c11[2][4][4], cx[2][4][4];
#pragma unroll
    for (int mt = 0; mt < 2; mt++)
#pragma unroll
        for (int nt = 0; nt < 4; nt++)
#pragma unroll
            for (int q = 0; q < 4; q++) { c11[mt][nt][q] = 0; cx[mt][nt][q] = 0; }

    const int a_row_sel = r8 + (g8 & 1) * 8;
    const int chunk16   = (g8 >> 1) * 16;

    int buf = 0;
#pragma unroll 1
    for (int kt = 0; kt < NSTAGE; kt++) {
        if (kt < NSTAGE - 1) asm volatile("cp.async.wait_group 1;" ::: "memory");
        else                 asm volatile("cp.async.wait_group 0;" ::: "memory");
        __syncthreads();

        // issue stage kt+2
        if (kt + 2 < NSTAGE) {
            int nb = buf + 2; if (nb >= NBUF) nb -= NBUF;
            uint32_t ab = sb + OFF_TILES + nb * STAGE_BYTES;
            const int kb = (kt + 2) * KCB;
#pragma unroll
            for (int i = 0; i < 2; i++) {
                int id = tid + i * NTHREADS;
                int row = id >> 3, c = id & 7;
                uint32_t so = swz(row * 128 + c * 16);
                size_t ga = (size_t)(m0 + row) * ENC_ + kb + c * 16;
                size_t gb = (size_t)(n0 + row) * ENC_ + kb + c * 16;
                cp16(ab + so,         g_aq1 + ga);
                cp16(ab + 16384 + so, g_aq2 + ga);
                cp16(ab + 32768 + so, g_wq1 + gb);
                cp16(ab + 49152 + so, g_wq2 + gb);
            }
            asm volatile("cp.async.commit_group;" ::: "memory");
        }

        // compute stage kt: 4 k32 steps
        const uint32_t st = sb + OFF_TILES + buf * STAGE_BYTES;
#pragma unroll
        for (int j = 0; j < 4; j++) {
            const uint32_t kby = j * 32 + chunk16;
            uint32_t aq1[2][4], aq2[2][4], bq1[2][4], bq2[2][4];
#pragma unroll
            for (int mt = 0; mt < 2; mt++) {
                uint32_t ro = swz((wm * 32 + mt * 16 + a_row_sel) * 128 + kby);
                ldsm4(aq1[mt], st + ro);
                ldsm4(aq2[mt], st + 16384 + ro);
            }
#pragma unroll
            for (int bt = 0; bt < 2; bt++) {
                uint32_t ro = swz((wn * 32 + bt * 16 + a_row_sel) * 128 + kby);
                ldsm4(bq1[bt], st + 32768 + ro);
                ldsm4(bq2[bt], st + 49152 + ro);
            }
            // chain 1: q1*p1 -> c11
#pragma unroll
            for (int mt = 0; mt < 2; mt++)
#pragma unroll
                for (int nt = 0; nt < 4; nt++)
                    imma16832(c11[mt][nt], aq1[mt], bq1[nt >> 1][nt & 1], bq1[nt >> 1][(nt & 1) + 2]);
            // chain 2: q1*p2 -> cx
#pragma unroll
            for (int mt = 0; mt < 2; mt++)
#pragma unroll
                for (int nt = 0; nt < 4; nt++)
                    imma16832(cx[mt][nt], aq1[mt], bq2[nt >> 1][nt & 1], bq2[nt >> 1][(nt & 1) + 2]);
            // chain 3: q2*p1 -> cx (same scale as chain 2: s1*t1/254)
#pragma unroll
            for (int mt = 0; mt < 2; mt++)
#pragma unroll
                for (int nt = 0; nt < 4; nt++)
                    imma16832(cx[mt][nt], aq2[mt], bq1[nt >> 1][nt & 1], bq1[nt >> 1][(nt & 1) + 2]);
        }
        if (++buf == NBUF) buf = 0;
    }

    // ---- fused epilogue: v . tanh(s1*t1*(D11 + Dx/254) + h) ----
    const int g = lane >> 2, q = lane & 3;
    float* red = (float*)(smem + OFF_RED);
    __syncthreads();
#pragma unroll
    for (int mt = 0; mt < 2; mt++) {
        const int row0 = wm * 32 + mt * 16 + g;
        const float sm0 = ss[row0], sm1 = ss[row0 + 8];
        float r0 = 0.f, r1 = 0.f;
#pragma unroll
        for (int nt = 0; nt < 4; nt++) {
            int n = wn * 32 + nt * 8 + q * 2;
            float tn0 = ts[n], tn1 = ts[n + 1];
            float h0 = hs[n], h1 = hs[n + 1], v0 = vs[n], v1 = vs[n + 1];
            float f0 = (float)c11[mt][nt][0] + (float)cx[mt][nt][0] * (1.f / 254.f);
            float f1 = (float)c11[mt][nt][1] + (float)cx[mt][nt][1] * (1.f / 254.f);
            float f2 = (float)c11[mt][nt][2] + (float)cx[mt][nt][2] * (1.f / 254.f);
            float f3 = (float)c11[mt][nt][3] + (float)cx[mt][nt][3] * (1.f / 254.f);
            r0 += v0 * tanh_ffma(sm0 * tn0 * f0 + h0) + v1 * tanh_ffma(sm0 * tn1 * f1 + h1);
            r1 += v0 * tanh_ffma(sm1 * tn0 * f2 + h0) + v1 * tanh_ffma(sm1 * tn1 * f3 + h1);
        }
#pragma unroll
        for (int msk = 1; msk <= 2; msk <<= 1) {
            r0 += __shfl_xor_sync(0xffffffff, r0, msk);
            r1 += __shfl_xor_sync(0xffffffff, r1, msk);
        }
        if (q == 0) {
            red[row0 * 4 + wn] = r0;
            red[(row0 + 8) * 4 + wn] = r1;
        }
    }
    __syncthreads();
    if (tid < 128)
        g_partial[(size_t)blockIdx.x * M_TOTAL + m0 + tid] =
            red[tid * 4] + red[tid * 4 + 1] + red[tid * 4 + 2] + red[tid * 4 + 3];
}

// ---------------- softmax (4 planes) ----------------
__global__ void softmax_kernel(float* __restrict__ out) {
    __shared__ float sc[S_];
    __shared__ float rb[256];
    const int b = blockIdx.x, tid = threadIdx.x;
    float lmax = -1e30f;
    for (int s = tid; s < S_; s += 256) {
        float x = g_partial[b * S_ + s] + g_partial[M_TOTAL + b * S_ + s]
                + g_partial[2 * M_TOTAL + b * S_ + s] + g_partial[3 * M_TOTAL + b * S_ + s];
        sc[s] = x;
        lmax = fmaxf(lmax, x);
    }
    rb[tid] = lmax; __syncthreads();
    for (int o = 128; o > 0; o >>= 1) {
        if (tid < o) rb[tid] = fmaxf(rb[tid], rb[tid + o]);
        __syncthreads();
    }
    const float m = rb[0]; __syncthreads();
    float ls = 0.f;
    for (int s = tid; s < S_; s += 256) {
        float e = __expf(sc[s] - m);
        sc[s] = e; ls += e;
    }
    rb[tid] = ls; __syncthreads();
    for (int o = 128; o > 0; o >>= 1) {
        if (tid < o) rb[tid] += rb[tid + o];
        __syncthreads();
    }
    const float inv = 1.f / rb[0]; __syncthreads();
    for (int s = tid; s < S_; s += 256)
        out[b * S_ + s] = sc[s] * inv;
}

// ---------------- launcher ----------------
extern "C" void kernel_launch(void* const* d_in, const int* in_sizes, int n_in,
                              void* d_out, int out_size) {
    const float* hidden = (const float*)d_in[0];
    const float* enc    = (const float*)d_in[1];
    const float* W      = (const float*)d_in[2];
    const float* bvec   = (const float*)d_in[3];
    const float* v      = (const float*)d_in[4];
    float* out          = (float*)d_out;

    cudaFuncSetAttribute(gemm_kernel, cudaFuncAttributeMaxDynamicSharedMemorySize, SMEM_DYN);

    quant_we_kernel<<<DEC_, 128>>>(W);
    quant_a_kernel<<<M_TOTAL, 128>>>(enc);
    hproj_kernel<<<dim3(4, B_), 128>>>(hidden, W, bvec);
    gemm_kernel<<<dim3(DEC_ / BN, M_TOTAL / BM), NTHREADS, SMEM_DYN>>>(v);
    softmax_kernel<<<B_, 256>>>(out);
}

// round 11
// speedup vs baseline: 2.1620x; 2.1620x over previous
#include <cuda_runtime.h>
#include <cuda_bf16.h>
#include <cstdint>
#include <math.h>

#define B_      32
#define S_      2048
#define ENC_    1024
#define DEC_    512
#define WROW    1536
#define M_TOTAL 65536

#define BM 128
#define BN 256
#define KC 64
#define NSTAGE 16
#define NTHREADS 512

// dynamic smem layout (from 1024-aligned base)
#define OFF_VS    0
#define OFF_HS    1024
#define OFF_RED   2048
#define OFF_TILES 4096
#define STAGE_BYTES 98304        // Ahi 16K + Alo 16K + Bhi 32K + Blo 32K
#define AHI_OFF(s) (OFF_TILES + (s) * STAGE_BYTES)
#define ALO_OFF(s) (AHI_OFF(s) + 16384)
#define BHI_OFF(s) (AHI_OFF(s) + 32768)
#define BLO_OFF(s) (AHI_OFF(s) + 65536)
#define SMEM_DYN (1024 + OFF_TILES + 2 * STAGE_BYTES)   // 201728

__device__ __align__(256) __nv_bfloat16 g_we_hi[DEC_ * ENC_];
__device__ __align__(256) __nv_bfloat16 g_we_lo[DEC_ * ENC_];
__device__ float g_hproj[B_ * DEC_];
__device__ float g_partial[2 * M_TOTAL];

// ---------------- helpers ----------------
__device__ __forceinline__ uint32_t smem_u32(const void* p) {
    uint32_t a;
    asm("{ .reg .u64 t; cvta.to.shared.u64 t, %1; cvt.u32.u64 %0, t; }" : "=r"(a) : "l"(p));
    return a;
}
__device__ __forceinline__ uint32_t swz(uint32_t o) { return o ^ ((o >> 3) & 0x70); }
__device__ __forceinline__ void cp16(uint32_t dst, const void* src) {
    asm volatile("cp.async.cg.shared.global [%0], [%1], 16;"
                 :: "r"(dst), "l"(__cvta_generic_to_global(src)) : "memory");
}
__device__ __forceinline__ uint32_t pk(__nv_bfloat16 a, __nv_bfloat16 b) {
    __nv_bfloat162 p; p.x = a; p.y = b;
    return *reinterpret_cast<uint32_t*>(&p);
}
__device__ __forceinline__ float tanh_ffma(float x) {
    float xc = fminf(fmaxf(x, -8.f), 8.f);
    float y  = xc * 2.88539008177793f;
    float t  = y + 12582912.f;
    int   k  = __float_as_int(t) - __float_as_int(12582912.f);
    float f  = y - (t - 12582912.f);
    float p = 1.3333558146e-3f;
    p = fmaf(p, f, 9.6181291076e-3f);
    p = fmaf(p, f, 5.5504108664e-2f);
    p = fmaf(p, f, 2.4022650696e-1f);
    p = fmaf(p, f, 6.9314718056e-1f);
    p = fmaf(p, f, 1.0f);
    float E = __int_as_float(__float_as_int(p) + (k << 23));
    float D = E + 1.f;
    float r = __int_as_float(0x7EF311C3 - __float_as_int(D));
    r = r * fmaf(-D, r, 2.f);
    r = r * fmaf(-D, r, 2.f);
    r = r * fmaf(-D, r, 2.f);
    return fmaf(-2.f, r, 1.f);
}
__device__ __forceinline__ void ldsm4(uint32_t* r, uint32_t addr) {
    asm volatile("ldmatrix.sync.aligned.m8n8.x4.shared.b16 {%0,%1,%2,%3}, [%4];"
                 : "=r"(r[0]), "=r"(r[1]), "=r"(r[2]), "=r"(r[3]) : "r"(addr));
}
__device__ __forceinline__ void mma16816(float* c, const uint32_t* a, uint32_t b0, uint32_t b1) {
    asm volatile("mma.sync.aligned.m16n8k16.row.col.f32.bf16.bf16.f32 "
                 "{%0,%1,%2,%3}, {%4,%5,%6,%7}, {%8,%9}, {%0,%1,%2,%3};"
                 : "+f"(c[0]), "+f"(c[1]), "+f"(c[2]), "+f"(c[3])
                 : "r"(a[0]), "r"(a[1]), "r"(a[2]), "r"(a[3]), "r"(b0), "r"(b1));
}

// ---------------- kernel 0: We -> bf16 hi/lo ----------------
__global__ void conv_we_kernel(const float* __restrict__ W) {
    const int d = blockIdx.x, t = threadIdx.x;
    float4 x = *reinterpret_cast<const float4*>(W + (size_t)d * WROW + DEC_ + t * 4);
    float e[4] = {x.x, x.y, x.z, x.w};
    __nv_bfloat16 h[4], l[4];
#pragma unroll
    for (int i = 0; i < 4; i++) {
        h[i] = __float2bfloat16(e[i]);
        l[i] = __float2bfloat16(e[i] - __bfloat162float(h[i]));
    }
    *reinterpret_cast<uint2*>(g_we_hi + d * ENC_ + t * 4) = make_uint2(pk(h[0],h[1]), pk(h[2],h[3]));
    *reinterpret_cast<uint2*>(g_we_lo + d * ENC_ + t * 4) = make_uint2(pk(l[0],l[1]), pk(l[2],l[3]));
}

// ---------------- kernel 1: hproj ----------------
__global__ void hproj_kernel(const float* __restrict__ hidden,
                             const float* __restrict__ W,
                             const float* __restrict__ bvec) {
    __shared__ float hid[DEC_];
    const int b = blockIdx.y;
    const int n = blockIdx.x * 128 + threadIdx.x;
    for (int i = threadIdx.x; i < DEC_; i += 128) hid[i] = hidden[b * DEC_ + i];
    __syncthreads();
    const float4* wr = reinterpret_cast<const float4*>(W + (size_t)n * WROW);
    float acc = bvec[n];
#pragma unroll 8
    for (int k = 0; k < DEC_ / 4; k++) {
        float4 w = wr[k];
        acc += hid[k*4]*w.x + hid[k*4+1]*w.y + hid[k*4+2]*w.z + hid[k*4+3]*w.w;
    }
    g_hproj[b * DEC_ + n] = acc;
}

// ---------------- kernel 2: HMMA GEMM, fused A-conversion + epilogue ----------------
__global__ __launch_bounds__(NTHREADS, 1)
void gemm_kernel(const float* __restrict__ enc, const float* __restrict__ v) {
    extern __shared__ char sraw[];
    uint32_t sb0 = smem_u32(sraw);
    uint32_t sb = (sb0 + 1023u) & ~1023u;
    char* smem = sraw + (sb - sb0);

    const int tid  = threadIdx.x;
    const int lane = tid & 31;
    const int w    = tid >> 5;          // 0..15
    const int wm   = w >> 2;            // 0..3  (M: 32 rows)
    const int wn   = w & 3;             // 0..3  (N: 64 cols)
    const int g8   = lane >> 3;
    const int r8   = lane & 7;
    const int n0   = blockIdx.x * BN;
    const int m0   = blockIdx.y * BM;
    const int batch = m0 >> 11;

    float* vs = (float*)(smem + OFF_VS);
    float* hs = (float*)(smem + OFF_HS);
    if (tid < 256) {
        vs[tid] = v[n0 + tid];
        hs[tid] = g_hproj[batch * DEC_ + n0 + tid];
    }

    // ---- A staging assignment: row = tid>>2 (0..127), 16 floats at (tid&3)*16 ----
    const int arow = tid >> 2;
    const int acol = (tid & 3) * 16;
    const float* aptr = enc + (size_t)(m0 + arow) * ENC_ + acol;
    uint32_t a_sts[4];                   // swizzled STS offsets (within A region)
#pragma unroll
    for (int j = 0; j < 4; j++) a_sts[j] = swz(arow * 128 + (acol + j * 4) * 2);

    // ---- B cp.async swizzled offsets ----
    uint32_t b_so[4];
    const int brow = tid >> 3, bc = tid & 7;
#pragma unroll
    for (int i = 0; i < 4; i++) b_so[i] = swz((brow + i * 64) * 128 + bc * 16);
    const __nv_bfloat16* gBh = g_we_hi + (size_t)(n0 + brow) * ENC_ + bc * 8;
    const __nv_bfloat16* gBl = g_we_lo + (size_t)(n0 + brow) * ENC_ + bc * 8;

    // ---- hoisted ldsm XOR-bases (chunk16 folded) ----
    const int a_row_sel = r8 + (g8 & 1) * 8;
    const int chunk16   = (g8 >> 1) * 16;
    uint32_t pA[2], pB[4];
#pragma unroll
    for (int mt = 0; mt < 2; mt++) {
        uint32_t R = (wm * 32 + mt * 16 + a_row_sel) * 128;
        pA[mt] = R + (chunk16 ^ ((R >> 3) & 0x70));
    }
#pragma unroll
    for (int ng = 0; ng < 4; ng++) {
        uint32_t R = (wn * 64 + ng * 16 + a_row_sel) * 128;
        pB[ng] = R + (chunk16 ^ ((R >> 3) & 0x70));
    }

    // ---- prologue: stage 0 A convert + B issue ----
    {
        float4 ar[4];
#pragma unroll
        for (int j = 0; j < 4; j++) ar[j] = *reinterpret_cast<const float4*>(aptr + j * 4);
        char* ah = smem + AHI_OFF(0);
        char* al = smem + ALO_OFF(0);
#pragma unroll
        for (int j = 0; j < 4; j++) {
            float e0=ar[j].x, e1=ar[j].y, e2=ar[j].z, e3=ar[j].w;
            __nv_bfloat16 h0=__float2bfloat16(e0), h1=__float2bfloat16(e1);
            __nv_bfloat16 h2=__float2bfloat16(e2), h3=__float2bfloat16(e3);
            __nv_bfloat16 l0=__float2bfloat16(e0-__bfloat162float(h0));
            __nv_bfloat16 l1=__float2bfloat16(e1-__bfloat162float(h1));
            __nv_bfloat16 l2=__float2bfloat16(e2-__bfloat162float(h2));
            __nv_bfloat16 l3=__float2bfloat16(e3-__bfloat162float(h3));
            *reinterpret_cast<uint2*>(ah + a_sts[j]) = make_uint2(pk(h0,h1), pk(h2,h3));
            *reinterpret_cast<uint2*>(al + a_sts[j]) = make_uint2(pk(l0,l1), pk(l2,l3));
        }
        uint32_t bh = sb + BHI_OFF(0), bl = sb + BLO_OFF(0);
#pragma unroll
        for (int i = 0; i < 4; i++) {
            cp16(bh + b_so[i], gBh + (size_t)i * 64 * ENC_);
            cp16(bl + b_so[i], gBl + (size_t)i * 64 * ENC_);
        }
        asm volatile("cp.async.commit_group;" ::: "memory");
    }

    float c[2][8][4];
#pragma unroll
    for (int mt = 0; mt < 2; mt++)
#pragma unroll
        for (int nt = 0; nt < 8; nt++)
#pragma unroll
            for (int q = 0; q < 4; q++) c[mt][nt][q] = 0.f;

#pragma unroll 1
    for (int kt = 0; kt < NSTAGE; kt++) {
        const int b = kt & 1;
        const int nb = b ^ 1;

        // LDG A(kt+1) fp32 (latency hidden behind wait+sync)
        float4 ar[4];
        if (kt + 1 < NSTAGE) {
            const int kb = (kt + 1) * KC;
#pragma unroll
            for (int j = 0; j < 4; j++)
                ar[j] = *reinterpret_cast<const float4*>(aptr + kb + j * 4);
        }

        asm volatile("cp.async.wait_group 0;" ::: "memory");
        __syncthreads();

        if (kt + 1 < NSTAGE) {
            // convert + STS A(kt+1) into buffer nb (its last readers synced above)
            char* ah = smem + AHI_OFF(nb);
            char* al = smem + ALO_OFF(nb);
#pragma unroll
            for (int j = 0; j < 4; j++) {
                float e0=ar[j].x, e1=ar[j].y, e2=ar[j].z, e3=ar[j].w;
                __nv_bfloat16 h0=__float2bfloat16(e0), h1=__float2bfloat16(e1);
                __nv_bfloat16 h2=__float2bfloat16(e2), h3=__float2bfloat16(e3);
                __nv_bfloat16 l0=__float2bfloat16(e0-__bfloat162float(h0));
                __nv_bfloat16 l1=__float2bfloat16(e1-__bfloat162float(h1));
                __nv_bfloat16 l2=__float2bfloat16(e2-__bfloat162float(h2));
                __nv_bfloat16 l3=__float2bfloat16(e3-__bfloat162float(h3));
                *reinterpret_cast<uint2*>(ah + a_sts[j]) = make_uint2(pk(h0,h1), pk(h2,h3));
                *reinterpret_cast<uint2*>(al + a_sts[j]) = make_uint2(pk(l0,l1), pk(l2,l3));
            }
            // issue B(kt+1)
            const int kb = (kt + 1) * KC;
            uint32_t bh = sb + BHI_OFF(nb), bl = sb + BLO_OFF(nb);
#pragma unroll
            for (int i = 0; i < 4; i++) {
                cp16(bh + b_so[i], gBh + (size_t)i * 64 * ENC_ + kb);
                cp16(bl + b_so[i], gBl + (size_t)i * 64 * ENC_ + kb);
            }
            asm volatile("cp.async.commit_group;" ::: "memory");
        }

        // compute stage kt
        const uint32_t ahb = sb + AHI_OFF(b), alb = sb + ALO_OFF(b);
        const uint32_t bhb = sb + BHI_OFF(b), blb = sb + BLO_OFF(b);
#pragma unroll
        for (int k16 = 0; k16 < 4; k16++) {
            const uint32_t kx = (uint32_t)(k16 << 5);
            uint32_t ah[2][4], al[2][4], bh[4][4], bl[4][4];
#pragma unroll
            for (int mt = 0; mt < 2; mt++) {
                ldsm4(ah[mt], (ahb + pA[mt]) ^ kx);
                ldsm4(al[mt], (alb + pA[mt]) ^ kx);
            }
#pragma unroll
            for (int ng = 0; ng < 4; ng++) {
                ldsm4(bh[ng], (bhb + pB[ng]) ^ kx);
                ldsm4(bl[ng], (blb + pB[ng]) ^ kx);
            }
#pragma unroll
            for (int mt = 0; mt < 2; mt++)
#pragma unroll
                for (int ng = 0; ng < 4; ng++)
#pragma unroll
                    for (int s = 0; s < 2; s++)
                        mma16816(c[mt][ng * 2 + s], ah[mt], bh[ng][s], bh[ng][s + 2]);
#pragma unroll
            for (int mt = 0; mt < 2; mt++)
#pragma unroll
                for (int ng = 0; ng < 4; ng++)
#pragma unroll
                    for (int s = 0; s < 2; s++)
                        mma16816(c[mt][ng * 2 + s], ah[mt], bl[ng][s], bl[ng][s + 2]);
#pragma unroll
            for (int mt = 0; mt < 2; mt++)
#pragma unroll
                for (int ng = 0; ng < 4; ng++)
#pragma unroll
                    for (int s = 0; s < 2; s++)
                        mma16816(c[mt][ng * 2 + s], al[mt], bh[ng][s], bh[ng][s + 2]);
        }
        __syncthreads();
    }

    // ---- fused epilogue: v . tanh(C + h) ----
    const int g = lane >> 2, q = lane & 3;
    float* red = (float*)(smem + OFF_RED);
#pragma unroll
    for (int mt = 0; mt < 2; mt++) {
        float r0 = 0.f, r1 = 0.f;
#pragma unroll
        for (int nt = 0; nt < 8; nt++) {
            int n = wn * 64 + nt * 8 + q * 2;
            float v0 = vs[n], v1 = vs[n + 1], h0 = hs[n], h1 = hs[n + 1];
            r0 += v0 * tanh_ffma(c[mt][nt][0] + h0) + v1 * tanh_ffma(c[mt][nt][1] + h1);
            r1 += v0 * tanh_ffma(c[mt][nt][2] + h0) + v1 * tanh_ffma(c[mt][nt][3] + h1);
        }
#pragma unroll
        for (int msk = 1; msk <= 2; msk <<= 1) {
            r0 += __shfl_xor_sync(0xffffffff, r0, msk);
            r1 += __shfl_xor_sync(0xffffffff, r1, msk);
        }
        if (q == 0) {
            int row = wm * 32 + mt * 16 + g;
            red[row * 4 + wn] = r0;
            red[(row + 8) * 4 + wn] = r1;
        }
    }
    __syncthreads();
    if (tid < 128)
        g_partial[(size_t)blockIdx.x * M_TOTAL + m0 + tid] =
            red[tid * 4] + red[tid * 4 + 1] + red[tid * 4 + 2] + red[tid * 4 + 3];
}

// ---------------- kernel 3: softmax ----------------
__global__ void softmax_kernel(float* __restrict__ out) {
    __shared__ float sc[S_];
    __shared__ float rb[256];
    const int b = blockIdx.x, tid = threadIdx.x;
    float lmax = -1e30f;
    for (int s = tid; s < S_; s += 256) {
        float x = g_partial[b * S_ + s] + g_partial[M_TOTAL + b * S_ + s];
        sc[s] = x;
        lmax = fmaxf(lmax, x);
    }
    rb[tid] = lmax; __syncthreads();
    for (int o = 128; o > 0; o >>= 1) {
        if (tid < o) rb[tid] = fmaxf(rb[tid], rb[tid + o]);
        __syncthreads();
    }
    const float m = rb[0]; __syncthreads();
    float ls = 0.f;
    for (int s = tid; s < S_; s += 256) {
        float e = __expf(sc[s] - m);
        sc[s] = e; ls += e;
    }
    rb[tid] = ls; __syncthreads();
    for (int o = 128; o > 0; o >>= 1) {
        if (tid < o) rb[tid] += rb[tid + o];
        __syncthreads();
    }
    const float inv = 1.f / rb[0]; __syncthreads();
    for (int s = tid; s < S_; s += 256)
        out[b * S_ + s] = sc[s] * inv;
}

// ---------------- launcher ----------------
extern "C" void kernel_launch(void* const* d_in, const int* in_sizes, int n_in,
                              void* d_out, int out_size) {
    const float* hidden = (const float*)d_in[0];
    const float* enc    = (const float*)d_in[1];
    const float* W      = (const float*)d_in[2];
    const float* bvec   = (const float*)d_in[3];
    const float* v      = (const float*)d_in[4];
    float* out          = (float*)d_out;

    cudaFuncSetAttribute(gemm_kernel, cudaFuncAttributeMaxDynamicSharedMemorySize, SMEM_DYN);

    conv_we_kernel<<<DEC_, 256>>>(W);
    hproj_kernel<<<dim3(4, B_), 128>>>(hidden, W, bvec);
    gemm_kernel<<<dim3(DEC_ / BN, M_TOTAL / BM), NTHREADS, SMEM_DYN>>>(enc, v);
    softmax_kernel<<<B_, 256>>>(out);
}

// round 12
// speedup vs baseline: 2.4593x; 1.1375x over previous
#include <cuda_runtime.h>
#include <cuda_bf16.h>
#include <cstdint>
#include <math.h>

#define B_      32
#define S_      2048
#define ENC_    1024
#define DEC_    512
#define WROW    1536
#define M_TOTAL 65536

#define BM 128
#define BN 256
#define KC 64
#define NSTAGE 16
#define NTHREADS 512

// dynamic smem layout (from 1024-aligned base)
#define OFF_VS    0
#define OFF_HS    1024
#define OFF_RED   2048
#define OFF_TILES 4096
#define STAGE_BYTES 98304        // Ahi 16K + Alo 16K + Bhi 32K + Blo 32K
#define AHI_OFF(s) (OFF_TILES + (s) * STAGE_BYTES)
#define ALO_OFF(s) (AHI_OFF(s) + 16384)
#define BHI_OFF(s) (AHI_OFF(s) + 32768)
#define BLO_OFF(s) (AHI_OFF(s) + 65536)
#define SMEM_DYN (1024 + OFF_TILES + 2 * STAGE_BYTES)   // 201728

__device__ __align__(256) __nv_bfloat16 g_we_hi[DEC_ * ENC_];
__device__ __align__(256) __nv_bfloat16 g_we_lo[DEC_ * ENC_];
__device__ __align__(256) __nv_bfloat16 g_a_hi[(size_t)M_TOTAL * ENC_];
__device__ __align__(256) __nv_bfloat16 g_a_lo[(size_t)M_TOTAL * ENC_];
__device__ float g_hproj[B_ * DEC_];
__device__ float g_partial[2 * M_TOTAL];

// ---------------- helpers ----------------
__device__ __forceinline__ uint32_t smem_u32(const void* p) {
    uint32_t a;
    asm("{ .reg .u64 t; cvta.to.shared.u64 t, %1; cvt.u32.u64 %0, t; }" : "=r"(a) : "l"(p));
    return a;
}
__device__ __forceinline__ uint32_t swz(uint32_t o) { return o ^ ((o >> 3) & 0x70); }
__device__ __forceinline__ void cp16(uint32_t dst, const void* src) {
    asm volatile("cp.async.cg.shared.global [%0], [%1], 16;"
                 :: "r"(dst), "l"(__cvta_generic_to_global(src)) : "memory");
}
__device__ __forceinline__ uint32_t pk(__nv_bfloat16 a, __nv_bfloat16 b) {
    __nv_bfloat162 p; p.x = a; p.y = b;
    return *reinterpret_cast<uint32_t*>(&p);
}
__device__ __forceinline__ float tanh_ffma(float x) {
    float xc = fminf(fmaxf(x, -8.f), 8.f);
    float y  = xc * 2.88539008177793f;
    float t  = y + 12582912.f;
    int   k  = __float_as_int(t) - __float_as_int(12582912.f);
    float f  = y - (t - 12582912.f);
    float p = 1.3333558146e-3f;
    p = fmaf(p, f, 9.6181291076e-3f);
    p = fmaf(p, f, 5.5504108664e-2f);
    p = fmaf(p, f, 2.4022650696e-1f);
    p = fmaf(p, f, 6.9314718056e-1f);
    p = fmaf(p, f, 1.0f);
    float E = __int_as_float(__float_as_int(p) + (k << 23));
    float D = E + 1.f;
    float r = __int_as_float(0x7EF311C3 - __float_as_int(D));
    r = r * fmaf(-D, r, 2.f);
    r = r * fmaf(-D, r, 2.f);
    r = r * fmaf(-D, r, 2.f);
    return fmaf(-2.f, r, 1.f);
}
__device__ __forceinline__ void ldsm4(uint32_t* r, uint32_t addr) {
    asm volatile("ldmatrix.sync.aligned.m8n8.x4.shared.b16 {%0,%1,%2,%3}, [%4];"
                 : "=r"(r[0]), "=r"(r[1]), "=r"(r[2]), "=r"(r[3]) : "r"(addr));
}
__device__ __forceinline__ void mma16816(float* c, const uint32_t* a, uint32_t b0, uint32_t b1) {
    asm volatile("mma.sync.aligned.m16n8k16.row.col.f32.bf16.bf16.f32 "
                 "{%0,%1,%2,%3}, {%4,%5,%6,%7}, {%8,%9}, {%0,%1,%2,%3};"
                 : "+f"(c[0]), "+f"(c[1]), "+f"(c[2]), "+f"(c[3])
                 : "r"(a[0]), "r"(a[1]), "r"(a[2]), "r"(a[3]), "r"(b0), "r"(b1));
}

// ---------------- kernel 0a: We -> bf16 hi/lo ----------------
__global__ void conv_we_kernel(const float* __restrict__ W) {
    const int d = blockIdx.x, t = threadIdx.x;
    float4 x = *reinterpret_cast<const float4*>(W + (size_t)d * WROW + DEC_ + t * 4);
    float e[4] = {x.x, x.y, x.z, x.w};
    __nv_bfloat16 h[4], l[4];
#pragma unroll
    for (int i = 0; i < 4; i++) {
        h[i] = __float2bfloat16(e[i]);
        l[i] = __float2bfloat16(e[i] - __bfloat162float(h[i]));
    }
    *reinterpret_cast<uint2*>(g_we_hi + d * ENC_ + t * 4) = make_uint2(pk(h[0],h[1]), pk(h[2],h[3]));
    *reinterpret_cast<uint2*>(g_we_lo + d * ENC_ + t * 4) = make_uint2(pk(l[0],l[1]), pk(l[2],l[3]));
}

// ---------------- kernel 0b: enc -> bf16 hi/lo ----------------
__global__ void conv_a_kernel(const float* __restrict__ enc) {
    size_t i = (size_t)blockIdx.x * blockDim.x + threadIdx.x;
    float4 x = reinterpret_cast<const float4*>(enc)[i];
    float e[4] = {x.x, x.y, x.z, x.w};
    __nv_bfloat16 h[4], l[4];
#pragma unroll
    for (int j = 0; j < 4; j++) {
        h[j] = __float2bfloat16(e[j]);
        l[j] = __float2bfloat16(e[j] - __bfloat162float(h[j]));
    }
    reinterpret_cast<uint2*>(g_a_hi)[i] = make_uint2(pk(h[0],h[1]), pk(h[2],h[3]));
    reinterpret_cast<uint2*>(g_a_lo)[i] = make_uint2(pk(l[0],l[1]), pk(l[2],l[3]));
}

// ---------------- kernel 1: hproj ----------------
__global__ void hproj_kernel(const float* __restrict__ hidden,
                             const float* __restrict__ W,
                             const float* __restrict__ bvec) {
    __shared__ float hid[DEC_];
    const int b = blockIdx.y;
    const int n = blockIdx.x * 128 + threadIdx.x;
    for (int i = threadIdx.x; i < DEC_; i += 128) hid[i] = hidden[b * DEC_ + i];
    __syncthreads();
    const float4* wr = reinterpret_cast<const float4*>(W + (size_t)n * WROW);
    float acc = bvec[n];
#pragma unroll 8
    for (int k = 0; k < DEC_ / 4; k++) {
        float4 w = wr[k];
        acc += hid[k*4]*w.x + hid[k*4+1]*w.y + hid[k*4+2]*w.z + hid[k*4+3]*w.w;
    }
    g_hproj[b * DEC_ + n] = acc;
}

// ---------------- kernel 2: HMMA GEMM + fused epilogue ----------------
__global__ __launch_bounds__(NTHREADS, 1)
void gemm_kernel(const float* __restrict__ v) {
    extern __shared__ char sraw[];
    uint32_t sb0 = smem_u32(sraw);
    uint32_t sb = (sb0 + 1023u) & ~1023u;
    char* smem = sraw + (sb - sb0);

    const int tid  = threadIdx.x;
    const int lane = tid & 31;
    const int w    = tid >> 5;          // 0..15
    const int wm   = w >> 2;            // 0..3  (M: 32 rows)
    const int wn   = w & 3;             // 0..3  (N: 64 cols)
    const int g8   = lane >> 3;
    const int r8   = lane & 7;
    const int n0   = blockIdx.x * BN;
    const int m0   = blockIdx.y * BM;
    const int batch = m0 >> 11;

    float* vs = (float*)(smem + OFF_VS);
    float* hs = (float*)(smem + OFF_HS);
    if (tid < 256) {
        vs[tid] = v[n0 + tid];
        hs[tid] = g_hproj[batch * DEC_ + n0 + tid];
    }

    // ---- hoisted ldsm row-bases + swizzle XOR masks ----
    const int a_row_sel = r8 + (g8 & 1) * 8;
    const uint32_t chunk16 = (uint32_t)((g8 >> 1) * 16);
    uint32_t fA[2], xA[2], fB[4], xB[4];
#pragma unroll
    for (int mt = 0; mt < 2; mt++) {
        uint32_t R = (uint32_t)((wm * 32 + mt * 16 + a_row_sel) * 128);
        fA[mt] = R; xA[mt] = (R >> 3) & 0x70;
    }
#pragma unroll
    for (int ng = 0; ng < 4; ng++) {
        uint32_t R = (uint32_t)((wn * 64 + ng * 16 + a_row_sel) * 128);
        fB[ng] = R; xB[ng] = (R >> 3) & 0x70;
    }

    // prologue: stage 0
    {
        uint32_t ah = sb + AHI_OFF(0), al = sb + ALO_OFF(0);
        uint32_t bh = sb + BHI_OFF(0), bl = sb + BLO_OFF(0);
#pragma unroll
        for (int i = 0; i < 2; i++) {
            int id = tid + i * NTHREADS;
            int row = id >> 3, c = id & 7;
            uint32_t so = swz(row * 128 + c * 16);
            size_t g = (size_t)(m0 + row) * ENC_ + c * 8;
            cp16(ah + so, g_a_hi + g);
            cp16(al + so, g_a_lo + g);
        }
#pragma unroll
        for (int i = 0; i < 4; i++) {
            int id = tid + i * NTHREADS;
            int row = id >> 3, c = id & 7;
            uint32_t so = swz(row * 128 + c * 16);
            size_t g = (size_t)(n0 + row) * ENC_ + c * 8;
            cp16(bh + so, g_we_hi + g);
            cp16(bl + so, g_we_lo + g);
        }
        asm volatile("cp.async.commit_group;" ::: "memory");
    }

    float c[2][8][4];
#pragma unroll
    for (int mt = 0; mt < 2; mt++)
#pragma unroll
        for (int nt = 0; nt < 8; nt++)
#pragma unroll
            for (int q = 0; q < 4; q++) c[mt][nt][q] = 0.f;

#pragma unroll 1
    for (int kt = 0; kt < NSTAGE; kt++) {
        const int b = kt & 1;
        asm volatile("cp.async.wait_group 0;" ::: "memory");
        __syncthreads();

        // issue loads for kt+1 (overlap with compute below)
        if (kt + 1 < NSTAGE) {
            const int nb = (kt + 1) & 1;
            const int kb = (kt + 1) * KC;
            uint32_t ah = sb + AHI_OFF(nb), al = sb + ALO_OFF(nb);
            uint32_t bh = sb + BHI_OFF(nb), bl = sb + BLO_OFF(nb);
#pragma unroll
            for (int i = 0; i < 2; i++) {
                int id = tid + i * NTHREADS;
                int row = id >> 3, cc = id & 7;
                uint32_t so = swz(row * 128 + cc * 16);
                size_t g = (size_t)(m0 + row) * ENC_ + kb + cc * 8;
                cp16(ah + so, g_a_hi + g);
                cp16(al + so, g_a_lo + g);
            }
#pragma unroll
            for (int i = 0; i < 4; i++) {
                int id = tid + i * NTHREADS;
                int row = id >> 3, cc = id & 7;
                uint32_t so = swz(row * 128 + cc * 16);
                size_t g = (size_t)(n0 + row) * ENC_ + kb + cc * 8;
                cp16(bh + so, g_we_hi + g);
                cp16(bl + so, g_we_lo + g);
            }
            asm volatile("cp.async.commit_group;" ::: "memory");
        }

        // compute stage kt: 4 k16 steps, hoisted addressing, 3 MMA sweeps
        const uint32_t ahb = sb + AHI_OFF(b);   // ALO = +16384, BLO = BHI + 32768
        const uint32_t bhb = sb + BHI_OFF(b);
#pragma unroll
        for (int k16 = 0; k16 < 4; k16++) {
            const uint32_t kk = (uint32_t)(k16 * 32) + chunk16;
            uint32_t ah[2][4], al[2][4], bh[4][4], bl[4][4];
#pragma unroll
            for (int mt = 0; mt < 2; mt++) {
                uint32_t q = fA[mt] + (kk ^ xA[mt]);
                ldsm4(ah[mt], ahb + q);
                ldsm4(al[mt], ahb + 16384 + q);
            }
#pragma unroll
            for (int ng = 0; ng < 4; ng++) {
                uint32_t q = fB[ng] + (kk ^ xB[ng]);
                ldsm4(bh[ng], bhb + q);
                ldsm4(bl[ng], bhb + 32768 + q);
            }
            // sweep 1: hi*hi
#pragma unroll
            for (int mt = 0; mt < 2; mt++)
#pragma unroll
                for (int ng = 0; ng < 4; ng++)
#pragma unroll
                    for (int s = 0; s < 2; s++)
                        mma16816(c[mt][ng * 2 + s], ah[mt], bh[ng][s], bh[ng][s + 2]);
            // sweep 2: hi*lo
#pragma unroll
            for (int mt = 0; mt < 2; mt++)
#pragma unroll
                for (int ng = 0; ng < 4; ng++)
#pragma unroll
                    for (int s = 0; s < 2; s++)
                        mma16816(c[mt][ng * 2 + s], ah[mt], bl[ng][s], bl[ng][s + 2]);
            // sweep 3: lo*hi
#pragma unroll
            for (int mt = 0; mt < 2; mt++)
#pragma unroll
                for (int ng = 0; ng < 4; ng++)
#pragma unroll
                    for (int s = 0; s < 2; s++)
                        mma16816(c[mt][ng * 2 + s], al[mt], bh[ng][s], bh[ng][s + 2]);
        }
        __syncthreads();
    }

    // ---- fused epilogue: v . tanh(C + h) ----
    const int g = lane >> 2, q = lane & 3;
    float* red = (float*)(smem + OFF_RED);
#pragma unroll
    for (int mt = 0; mt < 2; mt++) {
        float r0 = 0.f, r1 = 0.f;
#pragma unroll
        for (int nt = 0; nt < 8; nt++) {
            int n = wn * 64 + nt * 8 + q * 2;
            float v0 = vs[n], v1 = vs[n + 1], h0 = hs[n], h1 = hs[n + 1];
            r0 += v0 * tanh_ffma(c[mt][nt][0] + h0) + v1 * tanh_ffma(c[mt][nt][1] + h1);
            r1 += v0 * tanh_ffma(c[mt][nt][2] + h0) + v1 * tanh_ffma(c[mt][nt][3] + h1);
        }
#pragma unroll
        for (int msk = 1; msk <= 2; msk <<= 1) {
            r0 += __shfl_xor_sync(0xffffffff, r0, msk);
            r1 += __shfl_xor_sync(0xffffffff, r1, msk);
        }
        if (q == 0) {
            int row = wm * 32 + mt * 16 + g;
            red[row * 4 + wn] = r0;
            red[(row + 8) * 4 + wn] = r1;
        }
    }
    __syncthreads();
    if (tid < 128)
        g_partial[(size_t)blockIdx.x * M_TOTAL + m0 + tid] =
            red[tid * 4] + red[tid * 4 + 1] + red[tid * 4 + 2] + red[tid * 4 + 3];
}

// ---------------- kernel 3: softmax ----------------
__global__ void softmax_kernel(float* __restrict__ out) {
    __shared__ float sc[S_];
    __shared__ float rb[256];
    const int b = blockIdx.x, tid = threadIdx.x;
    float lmax = -1e30f;
    for (int s = tid; s < S_; s += 256) {
        float x = g_partial[b * S_ + s] + g_partial[M_TOTAL + b * S_ + s];
        sc[s] = x;
        lmax = fmaxf(lmax, x);
    }
    rb[tid] = lmax; __syncthreads();
    for (int o = 128; o > 0; o >>= 1) {
        if (tid < o) rb[tid] = fmaxf(rb[tid], rb[tid + o]);
        __syncthreads();
    }
    const float m = rb[0]; __syncthreads();
    float ls = 0.f;
    for (int s = tid; s < S_; s += 256) {
        float e = __expf(sc[s] - m);
        sc[s] = e; ls += e;
    }
    rb[tid] = ls; __syncthreads();
    for (int o = 128; o > 0; o >>= 1) {
        if (tid < o) rb[tid] += rb[tid + o];
        __syncthreads();
    }
    const float inv = 1.f / rb[0]; __syncthreads();
    for (int s = tid; s < S_; s += 256)
        out[b * S_ + s] = sc[s] * inv;
}

// ---------------- launcher ----------------
extern "C" void kernel_launch(void* const* d_in, const int* in_sizes, int n_in,
                              void* d_out, int out_size) {
    const float* hidden = (const float*)d_in[0];
    const float* enc    = (const float*)d_in[1];
    const float* W      = (const float*)d_in[2];
    const float* bvec   = (const float*)d_in[3];
    const float* v      = (const float*)d_in[4];
    float* out          = (float*)d_out;

    cudaFuncSetAttribute(gemm_kernel, cudaFuncAttributeMaxDynamicSharedMemorySize, SMEM_DYN);

    conv_we_kernel<<<DEC_, 256>>>(W);
    conv_a_kernel<<<(size_t)M_TOTAL * ENC_ / 4 / 256, 256>>>(enc);
    hproj_kernel<<<dim3(4, B_), 128>>>(hidden, W, bvec);
    gemm_kernel<<<dim3(DEC_ / BN, M_TOTAL / BM), NTHREADS, SMEM_DYN>>>(v);
    softmax_kernel<<<B_, 256>>>(out);
}

// round 13
// speedup vs baseline: 2.4933x; 1.0138x over previous
#include <cuda_runtime.h>
#include <cuda_bf16.h>
#include <cstdint>
#include <math.h>

#define B_      32
#define S_      2048
#define ENC_    1024
#define DEC_    512
#define WROW    1536
#define M_TOTAL 65536

#define BM 128
#define BN 256
#define KC 64
#define NSTAGE 16
#define NTHREADS 512

#define OFF_VS    0
#define OFF_HS    1024
#define OFF_RED   2048
#define OFF_TILES 4096
#define STAGE_BYTES 98304        // Ahi 16K + Alo 16K + Bhi 32K + Blo 32K
#define AHI_OFF(s) (OFF_TILES + (s) * STAGE_BYTES)
#define ALO_OFF(s) (AHI_OFF(s) + 16384)
#define BHI_OFF(s) (AHI_OFF(s) + 32768)
#define BLO_OFF(s) (AHI_OFF(s) + 65536)
#define SMEM_DYN (1024 + OFF_TILES + 2 * STAGE_BYTES)   // 201728

__device__ __align__(256) __nv_bfloat16 g_we_hi[DEC_ * ENC_];
__device__ __align__(256) __nv_bfloat16 g_we_lo[DEC_ * ENC_];
__device__ __align__(256) __nv_bfloat16 g_a_hi[(size_t)M_TOTAL * ENC_];
__device__ __align__(256) __nv_bfloat16 g_a_lo[(size_t)M_TOTAL * ENC_];
__device__ float g_hproj[B_ * DEC_];
__device__ float g_partial[2 * M_TOTAL];

// ---------------- helpers ----------------
__device__ __forceinline__ uint32_t smem_u32(const void* p) {
    uint32_t a;
    asm("{ .reg .u64 t; cvta.to.shared.u64 t, %1; cvt.u32.u64 %0, t; }" : "=r"(a) : "l"(p));
    return a;
}
__device__ __forceinline__ uint32_t swz(uint32_t o) { return o ^ ((o >> 3) & 0x70); }
__device__ __forceinline__ void cp16(uint32_t dst, const void* src) {
    asm volatile("cp.async.cg.shared.global [%0], [%1], 16;"
                 :: "r"(dst), "l"(__cvta_generic_to_global(src)) : "memory");
}
__device__ __forceinline__ uint32_t pk(__nv_bfloat16 a, __nv_bfloat16 b) {
    __nv_bfloat162 p; p.x = a; p.y = b;
    return *reinterpret_cast<uint32_t*>(&p);
}
__device__ __forceinline__ float tanh_ffma(float x) {
    float xc = fminf(fmaxf(x, -8.f), 8.f);
    float y  = xc * 2.88539008177793f;
    float t  = y + 12582912.f;
    int   k  = __float_as_int(t) - __float_as_int(12582912.f);
    float f  = y - (t - 12582912.f);
    float p = 1.3333558146e-3f;
    p = fmaf(p, f, 9.6181291076e-3f);
    p = fmaf(p, f, 5.5504108664e-2f);
    p = fmaf(p, f, 2.4022650696e-1f);
    p = fmaf(p, f, 6.9314718056e-1f);
    p = fmaf(p, f, 1.0f);
    float E = __int_as_float(__float_as_int(p) + (k << 23));
    float D = E + 1.f;
    float r = __int_as_float(0x7EF311C3 - __float_as_int(D));
    r = r * fmaf(-D, r, 2.f);
    r = r * fmaf(-D, r, 2.f);
    r = r * fmaf(-D, r, 2.f);
    return fmaf(-2.f, r, 1.f);
}
__device__ __forceinline__ void ldsm4(uint32_t* r, uint32_t addr) {
    asm volatile("ldmatrix.sync.aligned.m8n8.x4.shared.b16 {%0,%1,%2,%3}, [%4];"
                 : "=r"(r[0]), "=r"(r[1]), "=r"(r[2]), "=r"(r[3]) : "r"(addr));
}
__device__ __forceinline__ void mma16816(float* c, const uint32_t* a, uint32_t b0, uint32_t b1) {
    asm volatile("mma.sync.aligned.m16n8k16.row.col.f32.bf16.bf16.f32 "
                 "{%0,%1,%2,%3}, {%4,%5,%6,%7}, {%8,%9}, {%0,%1,%2,%3};"
                 : "+f"(c[0]), "+f"(c[1]), "+f"(c[2]), "+f"(c[3])
                 : "r"(a[0]), "r"(a[1]), "r"(a[2]), "r"(a[3]), "r"(b0), "r"(b1));
}

// ---------------- kernel 0a: We -> bf16 hi/lo ----------------
__global__ void conv_we_kernel(const float* __restrict__ W) {
    const int d = blockIdx.x, t = threadIdx.x;
    float4 x = *reinterpret_cast<const float4*>(W + (size_t)d * WROW + DEC_ + t * 4);
    float e[4] = {x.x, x.y, x.z, x.w};
    __nv_bfloat16 h[4], l[4];
#pragma unroll
    for (int i = 0; i < 4; i++) {
        h[i] = __float2bfloat16(e[i]);
        l[i] = __float2bfloat16(e[i] - __bfloat162float(h[i]));
    }
    *reinterpret_cast<uint2*>(g_we_hi + d * ENC_ + t * 4) = make_uint2(pk(h[0],h[1]), pk(h[2],h[3]));
    *reinterpret_cast<uint2*>(g_we_lo + d * ENC_ + t * 4) = make_uint2(pk(l[0],l[1]), pk(l[2],l[3]));
}

// ---------------- kernel 0b: enc -> bf16 hi/lo ----------------
__global__ void conv_a_kernel(const float* __restrict__ enc) {
    size_t i = (size_t)blockIdx.x * blockDim.x + threadIdx.x;
    float4 x = reinterpret_cast<const float4*>(enc)[i];
    float e[4] = {x.x, x.y, x.z, x.w};
    __nv_bfloat16 h[4], l[4];
#pragma unroll
    for (int j = 0; j < 4; j++) {
        h[j] = __float2bfloat16(e[j]);
        l[j] = __float2bfloat16(e[j] - __bfloat162float(h[j]));
    }
    reinterpret_cast<uint2*>(g_a_hi)[i] = make_uint2(pk(h[0],h[1]), pk(h[2],h[3]));
    reinterpret_cast<uint2*>(g_a_lo)[i] = make_uint2(pk(l[0],l[1]), pk(l[2],l[3]));
}

// ---------------- kernel 1: hproj ----------------
__global__ void hproj_kernel(const float* __restrict__ hidden,
                             const float* __restrict__ W,
                             const float* __restrict__ bvec) {
    __shared__ float hid[DEC_];
    const int b = blockIdx.y;
    const int n = blockIdx.x * 128 + threadIdx.x;
    for (int i = threadIdx.x; i < DEC_; i += 128) hid[i] = hidden[b * DEC_ + i];
    __syncthreads();
    const float4* wr = reinterpret_cast<const float4*>(W + (size_t)n * WROW);
    float acc = bvec[n];
#pragma unroll 8
    for (int k = 0; k < DEC_ / 4; k++) {
        float4 w = wr[k];
        acc += hid[k*4]*w.x + hid[k*4+1]*w.y + hid[k*4+2]*w.z + hid[k*4+3]*w.w;
    }
    g_hproj[b * DEC_ + n] = acc;
}

// ---------------- kernel 2: HMMA GEMM + fused epilogue ----------------
__global__ __launch_bounds__(NTHREADS, 1)
void gemm_kernel(const float* __restrict__ v) {
    extern __shared__ char sraw[];
    uint32_t sb0 = smem_u32(sraw);
    uint32_t sb = (sb0 + 1023u) & ~1023u;
    char* smem = sraw + (sb - sb0);

    const int tid  = threadIdx.x;
    const int lane = tid & 31;
    const int w    = tid >> 5;          // 0..15
    const int wm   = w >> 2;            // 0..3  (M: 32 rows) — also SMSP-distinct rotation
    const int wn   = w & 3;             // 0..3  (N: 64 cols)
    const int g8   = lane >> 3;
    const int r8   = lane & 7;
    const int n0   = blockIdx.x * BN;
    const int m0   = blockIdx.y * BM;
    const int batch = m0 >> 11;

    float* vs = (float*)(smem + OFF_VS);
    float* hs = (float*)(smem + OFF_HS);
    if (tid < 256) {
        vs[tid] = v[n0 + tid];
        hs[tid] = g_hproj[batch * DEC_ + n0 + tid];
    }

    // hoisted ldsm row-bases + swizzle XOR masks
    const int a_row_sel = r8 + (g8 & 1) * 8;
    const uint32_t chunk16 = (uint32_t)((g8 >> 1) * 16);
    uint32_t fA[2], xA[2], fB[4], xB[4];
#pragma unroll
    for (int mt = 0; mt < 2; mt++) {
        uint32_t R = (uint32_t)((wm * 32 + mt * 16 + a_row_sel) * 128);
        fA[mt] = R; xA[mt] = (R >> 3) & 0x70;
    }
#pragma unroll
    for (int ng = 0; ng < 4; ng++) {
        uint32_t R = (uint32_t)((wn * 64 + ng * 16 + a_row_sel) * 128);
        fB[ng] = R; xB[ng] = (R >> 3) & 0x70;
    }

    // prologue: stage 0
    {
        uint32_t ah = sb + AHI_OFF(0), al = sb + ALO_OFF(0);
        uint32_t bh = sb + BHI_OFF(0), bl = sb + BLO_OFF(0);
#pragma unroll
        for (int i = 0; i < 2; i++) {
            int id = tid + i * NTHREADS;
            int row = id >> 3, c = id & 7;
            uint32_t so = swz(row * 128 + c * 16);
            size_t g = (size_t)(m0 + row) * ENC_ + c * 8;
            cp16(ah + so, g_a_hi + g);
            cp16(al + so, g_a_lo + g);
        }
#pragma unroll
        for (int i = 0; i < 4; i++) {
            int id = tid + i * NTHREADS;
            int row = id >> 3, c = id & 7;
            uint32_t so = swz(row * 128 + c * 16);
            size_t g = (size_t)(n0 + row) * ENC_ + c * 8;
            cp16(bh + so, g_we_hi + g);
            cp16(bl + so, g_we_lo + g);
        }
        asm volatile("cp.async.commit_group;" ::: "memory");
    }

    float c[2][8][4];
#pragma unroll
    for (int mt = 0; mt < 2; mt++)
#pragma unroll
        for (int nt = 0; nt < 8; nt++)
#pragma unroll
            for (int q = 0; q < 4; q++) c[mt][nt][q] = 0.f;

#pragma unroll 1
    for (int kt = 0; kt < NSTAGE; kt++) {
        const int b = kt & 1;
        asm volatile("cp.async.wait_group 0;" ::: "memory");
        __syncthreads();   // single sync: also protects buffer b^1 reuse below

        // issue loads for kt+1
        if (kt + 1 < NSTAGE) {
            const int nb = (kt + 1) & 1;
            const int kb = (kt + 1) * KC;
            uint32_t ah = sb + AHI_OFF(nb), al = sb + ALO_OFF(nb);
            uint32_t bh = sb + BHI_OFF(nb), bl = sb + BLO_OFF(nb);
#pragma unroll
            for (int i = 0; i < 2; i++) {
                int id = tid + i * NTHREADS;
                int row = id >> 3, cc = id & 7;
                uint32_t so = swz(row * 128 + cc * 16);
                size_t g = (size_t)(m0 + row) * ENC_ + kb + cc * 8;
                cp16(ah + so, g_a_hi + g);
                cp16(al + so, g_a_lo + g);
            }
#pragma unroll
            for (int i = 0; i < 4; i++) {
                int id = tid + i * NTHREADS;
                int row = id >> 3, cc = id & 7;
                uint32_t so = swz(row * 128 + cc * 16);
                size_t g = (size_t)(n0 + row) * ENC_ + kb + cc * 8;
                cp16(bh + so, g_we_hi + g);
                cp16(bl + so, g_we_lo + g);
            }
            asm volatile("cp.async.commit_group;" ::: "memory");
        }

        // compute stage kt: 4 k16 steps, per-SMSP rotated start to de-phase LDS bursts
        const uint32_t ahb = sb + AHI_OFF(b);   // ALO = +16384, BLO = BHI + 32768
        const uint32_t bhb = sb + BHI_OFF(b);
#pragma unroll
        for (int kq = 0; kq < 4; kq++) {
            const int k16 = (kq + wm) & 3;
            const uint32_t kk = (uint32_t)(k16 * 32) + chunk16;
            uint32_t ah[2][4], al[2][4], bh[4][4], bl[4][4];
#pragma unroll
            for (int mt = 0; mt < 2; mt++) {
                uint32_t q = fA[mt] + (kk ^ xA[mt]);
                ldsm4(ah[mt], ahb + q);
                ldsm4(al[mt], ahb + 16384 + q);
            }
#pragma unroll
            for (int ng = 0; ng < 4; ng++) {
                uint32_t q = fB[ng] + (kk ^ xB[ng]);
                ldsm4(bh[ng], bhb + q);
                ldsm4(bl[ng], bhb + 32768 + q);
            }
            // sweep 1: hi*hi
#pragma unroll
            for (int mt = 0; mt < 2; mt++)
#pragma unroll
                for (int ng = 0; ng < 4; ng++)
#pragma unroll
                    for (int s = 0; s < 2; s++)
                        mma16816(c[mt][ng * 2 + s], ah[mt], bh[ng][s], bh[ng][s + 2]);
            // sweep 2: hi*lo
#pragma unroll
            for (int mt = 0; mt < 2; mt++)
#pragma unroll
                for (int ng = 0; ng < 4; ng++)
#pragma unroll
                    for (int s = 0; s < 2; s++)
                        mma16816(c[mt][ng * 2 + s], ah[mt], bl[ng][s], bl[ng][s + 2]);
            // sweep 3: lo*hi
#pragma unroll
            for (int mt = 0; mt < 2; mt++)
#pragma unroll
                for (int ng = 0; ng < 4; ng++)
#pragma unroll
                    for (int s = 0; s < 2; s++)
                        mma16816(c[mt][ng * 2 + s], al[mt], bh[ng][s], bh[ng][s + 2]);
        }
        // (no bottom sync: top sync of next iteration protects buffer reuse)
    }

    // ---- fused epilogue: v . tanh(C + h) ----
    const int g = lane >> 2, q = lane & 3;
    float* red = (float*)(smem + OFF_RED);
#pragma unroll
    for (int mt = 0; mt < 2; mt++) {
        float r0 = 0.f, r1 = 0.f;
#pragma unroll
        for (int nt = 0; nt < 8; nt++) {
            int n = wn * 64 + nt * 8 + q * 2;
            float v0 = vs[n], v1 = vs[n + 1], h0 = hs[n], h1 = hs[n + 1];
            r0 += v0 * tanh_ffma(c[mt][nt][0] + h0) + v1 * tanh_ffma(c[mt][nt][1] + h1);
            r1 += v0 * tanh_ffma(c[mt][nt][2] + h0) + v1 * tanh_ffma(c[mt][nt][3] + h1);
        }
#pragma unroll
        for (int msk = 1; msk <= 2; msk <<= 1) {
            r0 += __shfl_xor_sync(0xffffffff, r0, msk);
            r1 += __shfl_xor_sync(0xffffffff, r1, msk);
        }
        if (q == 0) {
            int row = wm * 32 + mt * 16 + g;
            red[row * 4 + wn] = r0;
            red[(row + 8) * 4 + wn] = r1;
        }
    }
    __syncthreads();
    if (tid < 128)
        g_partial[(size_t)blockIdx.x * M_TOTAL + m0 + tid] =
            red[tid * 4] + red[tid * 4 + 1] + red[tid * 4 + 2] + red[tid * 4 + 3];
}

// ---------------- kernel 3: softmax ----------------
__global__ void softmax_kernel(float* __restrict__ out) {
    __shared__ float sc[S_];
    __shared__ float rb[256];
    const int b = blockIdx.x, tid = threadIdx.x;
    float lmax = -1e30f;
    for (int s = tid; s < S_; s += 256) {
        float x = g_partial[b * S_ + s] + g_partial[M_TOTAL + b * S_ + s];
        sc[s] = x;
        lmax = fmaxf(lmax, x);
    }
    rb[tid] = lmax; __syncthreads();
    for (int o = 128; o > 0; o >>= 1) {
        if (tid < o) rb[tid] = fmaxf(rb[tid], rb[tid + o]);
        __syncthreads();
    }
    const float m = rb[0]; __syncthreads();
    float ls = 0.f;
    for (int s = tid; s < S_; s += 256) {
        float e = __expf(sc[s] - m);
        sc[s] = e; ls += e;
    }
    rb[tid] = ls; __syncthreads();
    for (int o = 128; o > 0; o >>= 1) {
        if (tid < o) rb[tid] += rb[tid + o];
        __syncthreads();
    }
    const float inv = 1.f / rb[0]; __syncthreads();
    for (int s = tid; s < S_; s += 256)
        out[b * S_ + s] = sc[s] * inv;
}

// ---------------- launcher ----------------
extern "C" void kernel_launch(void* const* d_in, const int* in_sizes, int n_in,
                              void* d_out, int out_size) {
    const float* hidden = (const float*)d_in[0];
    const float* enc    = (const float*)d_in[1];
    const float* W      = (const float*)d_in[2];
    const float* bvec   = (const float*)d_in[3];
    const float* v      = (const float*)d_in[4];
    float* out          = (float*)d_out;

    cudaFuncSetAttribute(gemm_kernel, cudaFuncAttributeMaxDynamicSharedMemorySize, SMEM_DYN);

    conv_we_kernel<<<DEC_, 256>>>(W);
    conv_a_kernel<<<(size_t)M_TOTAL * ENC_ / 4 / 256, 256>>>(enc);
    hproj_kernel<<<dim3(4, B_), 128>>>(hidden, W, bvec);
    gemm_kernel<<<dim3(DEC_ / BN, M_TOTAL / BM), NTHREADS, SMEM_DYN>>>(v);
    softmax_kernel<<<B_, 256>>>(out);
}

// round 14
// speedup vs baseline: 2.5313x; 1.0152x over previous
#include <cuda_runtime.h>
#include <cuda_bf16.h>
#include <cstdint>
#include <math.h>

#define B_      32
#define S_      2048
#define ENC_    1024
#define DEC_    512
#define WROW    1536
#define M_TOTAL 65536

#define BM 128
#define BN 256
#define KC 32
#define NSTAGE 32
#define NTHREADS 512

// smem (from 1024-aligned base)
#define OFF_VS    0
#define OFF_HS    1024
#define OFF_RED   2048
#define OFF_TILES 4096
#define STAGE_BYTES 65536        // AF32 16K | ABF 16K (hi|lo per 128B row) | BBF 32K (hi|lo per row)
#define AF_OFF(s)  (OFF_TILES + (s) * STAGE_BYTES)
#define ABF_OFF(s) (AF_OFF(s) + 16384)
#define BBF_OFF(s) (AF_OFF(s) + 32768)
#define SMEM_DYN (1024 + OFF_TILES + 2 * STAGE_BYTES)   // 136192

__device__ __align__(256) __nv_bfloat16 g_we_hi[DEC_ * ENC_];
__device__ __align__(256) __nv_bfloat16 g_we_lo[DEC_ * ENC_];
__device__ float g_hproj[B_ * DEC_];
__device__ float g_partial[2 * M_TOTAL];

// ---------------- helpers ----------------
__device__ __forceinline__ uint32_t smem_u32(const void* p) {
    uint32_t a;
    asm("{ .reg .u64 t; cvta.to.shared.u64 t, %1; cvt.u32.u64 %0, t; }" : "=r"(a) : "l"(p));
    return a;
}
__device__ __forceinline__ uint32_t swz(uint32_t o) { return o ^ ((o >> 3) & 0x70); }
__device__ __forceinline__ void cp16(uint32_t dst, const void* src) {
    asm volatile("cp.async.cg.shared.global [%0], [%1], 16;"
                 :: "r"(dst), "l"(__cvta_generic_to_global(src)) : "memory");
}
__device__ __forceinline__ uint32_t pk(__nv_bfloat16 a, __nv_bfloat16 b) {
    __nv_bfloat162 p; p.x = a; p.y = b;
    return *reinterpret_cast<uint32_t*>(&p);
}
__device__ __forceinline__ float tanh_ffma(float x) {
    float xc = fminf(fmaxf(x, -8.f), 8.f);
    float y  = xc * 2.88539008177793f;
    float t  = y + 12582912.f;
    int   k  = __float_as_int(t) - __float_as_int(12582912.f);
    float f  = y - (t - 12582912.f);
    float p = 1.3333558146e-3f;
    p = fmaf(p, f, 9.6181291076e-3f);
    p = fmaf(p, f, 5.5504108664e-2f);
    p = fmaf(p, f, 2.4022650696e-1f);
    p = fmaf(p, f, 6.9314718056e-1f);
    p = fmaf(p, f, 1.0f);
    float E = __int_as_float(__float_as_int(p) + (k << 23));
    float D = E + 1.f;
    float r = __int_as_float(0x7EF311C3 - __float_as_int(D));
    r = r * fmaf(-D, r, 2.f);
    r = r * fmaf(-D, r, 2.f);
    r = r * fmaf(-D, r, 2.f);
    return fmaf(-2.f, r, 1.f);
}
__device__ __forceinline__ void ldsm4(uint32_t* r, uint32_t addr) {
    asm volatile("ldmatrix.sync.aligned.m8n8.x4.shared.b16 {%0,%1,%2,%3}, [%4];"
                 : "=r"(r[0]), "=r"(r[1]), "=r"(r[2]), "=r"(r[3]) : "r"(addr));
}
__device__ __forceinline__ void mma16816(float* c, const uint32_t* a, uint32_t b0, uint32_t b1) {
    asm volatile("mma.sync.aligned.m16n8k16.row.col.f32.bf16.bf16.f32 "
                 "{%0,%1,%2,%3}, {%4,%5,%6,%7}, {%8,%9}, {%0,%1,%2,%3};"
                 : "+f"(c[0]), "+f"(c[1]), "+f"(c[2]), "+f"(c[3])
                 : "r"(a[0]), "r"(a[1]), "r"(a[2]), "r"(a[3]), "r"(b0), "r"(b1));
}

// ---------------- kernel 0: We -> bf16 hi/lo ----------------
__global__ void conv_we_kernel(const float* __restrict__ W) {
    const int d = blockIdx.x, t = threadIdx.x;
    float4 x = *reinterpret_cast<const float4*>(W + (size_t)d * WROW + DEC_ + t * 4);
    float e[4] = {x.x, x.y, x.z, x.w};
    __nv_bfloat16 h[4], l[4];
#pragma unroll
    for (int i = 0; i < 4; i++) {
        h[i] = __float2bfloat16(e[i]);
        l[i] = __float2bfloat16(e[i] - __bfloat162float(h[i]));
    }
    *reinterpret_cast<uint2*>(g_we_hi + d * ENC_ + t * 4) = make_uint2(pk(h[0],h[1]), pk(h[2],h[3]));
    *reinterpret_cast<uint2*>(g_we_lo + d * ENC_ + t * 4) = make_uint2(pk(l[0],l[1]), pk(l[2],l[3]));
}

// ---------------- kernel 1: hproj ----------------
__global__ void hproj_kernel(const float* __restrict__ hidden,
                             const float* __restrict__ W,
                             const float* __restrict__ bvec) {
    __shared__ float hid[DEC_];
    const int b = blockIdx.y;
    const int n = blockIdx.x * 128 + threadIdx.x;
    for (int i = threadIdx.x; i < DEC_; i += 128) hid[i] = hidden[b * DEC_ + i];
    __syncthreads();
    const float4* wr = reinterpret_cast<const float4*>(W + (size_t)n * WROW);
    float acc = bvec[n];
#pragma unroll 8
    for (int k = 0; k < DEC_ / 4; k++) {
        float4 w = wr[k];
        acc += hid[k*4]*w.x + hid[k*4+1]*w.y + hid[k*4+2]*w.z + hid[k*4+3]*w.w;
    }
    g_hproj[b * DEC_ + n] = acc;
}

// ---------------- kernel 2: HMMA GEMM, cp.async A-fp32 + in-loop convert ----------------
__global__ __launch_bounds__(NTHREADS, 1)
void gemm_kernel(const float* __restrict__ enc, const float* __restrict__ v) {
    extern __shared__ char sraw[];
    uint32_t sb0 = smem_u32(sraw);
    uint32_t sb = (sb0 + 1023u) & ~1023u;
    char* smem = sraw + (sb - sb0);

    const int tid  = threadIdx.x;
    const int lane = tid & 31;
    const int w    = tid >> 5;          // 0..15
    const int wm   = w >> 2;            // 0..3  (M: 32 rows)
    const int wn   = w & 3;             // 0..3  (N: 64 cols)
    const int g8   = lane >> 3;
    const int r8   = lane & 7;
    const int n0   = blockIdx.x * BN;
    const int m0   = blockIdx.y * BM;
    const int batch = m0 >> 11;

    float* vs = (float*)(smem + OFF_VS);
    float* hs = (float*)(smem + OFF_HS);
    if (tid < 256) {
        vs[tid] = v[n0 + tid];
        hs[tid] = g_hproj[batch * DEC_ + n0 + tid];
    }

    // hoisted ldsm row-bases + swizzle XOR masks (hi|lo interleaved: lo = hi_addr ^ 64)
    const int a_row_sel = r8 + (g8 & 1) * 8;
    const uint32_t chunk16 = (uint32_t)((g8 >> 1) * 16);
    uint32_t fA[2], xA[2], fB[4], xB[4];
#pragma unroll
    for (int mt = 0; mt < 2; mt++) {
        uint32_t R = (uint32_t)((wm * 32 + mt * 16 + a_row_sel) * 128);
        fA[mt] = R; xA[mt] = (R >> 3) & 0x70;
    }
#pragma unroll
    for (int ng = 0; ng < 4; ng++) {
        uint32_t R = (uint32_t)((wn * 64 + ng * 16 + a_row_sel) * 128);
        fB[ng] = R; xB[ng] = (R >> 3) & 0x70;
    }

    // cp.async assignments (hoisted)
    const int arow = tid >> 3, ac = tid & 7;              // A fp32: 2 chunks (rows arow, arow+64)
    const int conv_row = tid >> 2, conv_c = tid & 3;      // convert: 8 floats

    // ---- prologue ----
    {   // group 1: A-fp32(0)
        uint32_t fb = sb + AF_OFF(0);
#pragma unroll
        for (int i = 0; i < 2; i++)
            cp16(fb + (arow + i * 64) * 128 + ac * 16,
                 enc + (size_t)(m0 + arow + i * 64) * ENC_ + ac * 4);
        asm volatile("cp.async.commit_group;" ::: "memory");
        // group 2: A-fp32(1) + B(0)
        uint32_t fb1 = sb + AF_OFF(1);
#pragma unroll
        for (int i = 0; i < 2; i++)
            cp16(fb1 + (arow + i * 64) * 128 + ac * 16,
                 enc + (size_t)(m0 + arow + i * 64) * ENC_ + KC + ac * 4);
        uint32_t bb = sb + BBF_OFF(0);
#pragma unroll
        for (int i = 0; i < 4; i++) {
            int id = tid + i * NTHREADS;
            int sel = id >> 10, rem = id & 1023;
            int row = rem >> 2, c = rem & 3;
            const __nv_bfloat16* src = (sel ? g_we_lo : g_we_hi) + (size_t)(n0 + row) * ENC_ + c * 8;
            cp16(bb + swz(row * 128 + sel * 64 + c * 16), src);
        }
        asm volatile("cp.async.commit_group;" ::: "memory");
        asm volatile("cp.async.wait_group 0;" ::: "memory");
        __syncthreads();
        // convert A(0): fp32 smem -> bf16 hi|lo smem
        const char* fsrc = smem + AF_OFF(0);
        char* adst = smem + ABF_OFF(0);
        float4 x0 = *reinterpret_cast<const float4*>(fsrc + conv_row * 128 + conv_c * 32);
        float4 x1 = *reinterpret_cast<const float4*>(fsrc + conv_row * 128 + conv_c * 32 + 16);
        float e[8] = {x0.x,x0.y,x0.z,x0.w,x1.x,x1.y,x1.z,x1.w};
        uint32_t hp[4], lp[4];
#pragma unroll
        for (int j = 0; j < 4; j++) {
            __nv_bfloat16 h0 = __float2bfloat16(e[j*2]),   h1 = __float2bfloat16(e[j*2+1]);
            __nv_bfloat16 l0 = __float2bfloat16(e[j*2]   - __bfloat162float(h0));
            __nv_bfloat16 l1 = __float2bfloat16(e[j*2+1] - __bfloat162float(h1));
            hp[j] = pk(h0, h1); lp[j] = pk(l0, l1);
        }
        uint32_t so = swz(conv_row * 128 + conv_c * 16);
        *reinterpret_cast<uint4*>(adst + so)        = make_uint4(hp[0],hp[1],hp[2],hp[3]);
        *reinterpret_cast<uint4*>(adst + (so ^ 64)) = make_uint4(lp[0],lp[1],lp[2],lp[3]);
    }

    float c[2][8][4];
#pragma unroll
    for (int mt = 0; mt < 2; mt++)
#pragma unroll
        for (int nt = 0; nt < 8; nt++)
#pragma unroll
            for (int q = 0; q < 4; q++) c[mt][nt][q] = 0.f;

#pragma unroll 1
    for (int kt = 0; kt < NSTAGE; kt++) {
        const int b = kt & 1;
        asm volatile("cp.async.wait_group 0;" ::: "memory");
        __syncthreads();

        // convert A(kt+1) fp32 -> bf16 hi|lo
        if (kt + 1 < NSTAGE) {
            const int nb = b ^ 1;
            const char* fsrc = smem + AF_OFF(nb);
            char* adst = smem + ABF_OFF(nb);
            float4 x0 = *reinterpret_cast<const float4*>(fsrc + conv_row * 128 + conv_c * 32);
            float4 x1 = *reinterpret_cast<const float4*>(fsrc + conv_row * 128 + conv_c * 32 + 16);
            float e[8] = {x0.x,x0.y,x0.z,x0.w,x1.x,x1.y,x1.z,x1.w};
            uint32_t hp[4], lp[4];
#pragma unroll
            for (int j = 0; j < 4; j++) {
                __nv_bfloat16 h0 = __float2bfloat16(e[j*2]),   h1 = __float2bfloat16(e[j*2+1]);
                __nv_bfloat16 l0 = __float2bfloat16(e[j*2]   - __bfloat162float(h0));
                __nv_bfloat16 l1 = __float2bfloat16(e[j*2+1] - __bfloat162float(h1));
                hp[j] = pk(h0, h1); lp[j] = pk(l0, l1);
            }
            uint32_t so = swz(conv_row * 128 + conv_c * 16);
            *reinterpret_cast<uint4*>(adst + so)        = make_uint4(hp[0],hp[1],hp[2],hp[3]);
            *reinterpret_cast<uint4*>(adst + (so ^ 64)) = make_uint4(lp[0],lp[1],lp[2],lp[3]);
        }

        // issue cp.async: A-fp32(kt+2) + B(kt+1)
        if (kt + 2 < NSTAGE) {
            uint32_t fb = sb + AF_OFF(b);              // (kt+2)&1 == b
            const int kb = (kt + 2) * KC;
#pragma unroll
            for (int i = 0; i < 2; i++)
                cp16(fb + (arow + i * 64) * 128 + ac * 16,
                     enc + (size_t)(m0 + arow + i * 64) * ENC_ + kb + ac * 4);
        }
        if (kt + 1 < NSTAGE) {
            uint32_t bb = sb + BBF_OFF(b ^ 1);
            const int kb = (kt + 1) * KC;
#pragma unroll
            for (int i = 0; i < 4; i++) {
                int id = tid + i * NTHREADS;
                int sel = id >> 10, rem = id & 1023;
                int row = rem >> 2, cc = rem & 3;
                const __nv_bfloat16* src = (sel ? g_we_lo : g_we_hi) + (size_t)(n0 + row) * ENC_ + kb + cc * 8;
                cp16(bb + swz(row * 128 + sel * 64 + cc * 16), src);
            }
        }
        asm volatile("cp.async.commit_group;" ::: "memory");

        // compute stage kt: 2 k16 steps, 3 MMA sweeps each
        const uint32_t abf = sb + ABF_OFF(b);
        const uint32_t bbf = sb + BBF_OFF(b);
#pragma unroll
        for (int kq = 0; kq < 2; kq++) {
            const int k16 = (kq + wm) & 1;
            const uint32_t kk = (uint32_t)(k16 * 32) + chunk16;
            uint32_t ah[2][4], al[2][4], bh[4][4], bl[4][4];
#pragma unroll
            for (int mt = 0; mt < 2; mt++) {
                uint32_t q = abf + fA[mt] + (kk ^ xA[mt]);
                ldsm4(ah[mt], q);
                ldsm4(al[mt], q ^ 64);
            }
#pragma unroll
            for (int ng = 0; ng < 4; ng++) {
                uint32_t q = bbf + fB[ng] + (kk ^ xB[ng]);
                ldsm4(bh[ng], q);
                ldsm4(bl[ng], q ^ 64);
            }
#pragma unroll
            for (int mt = 0; mt < 2; mt++)
#pragma unroll
                for (int ng = 0; ng < 4; ng++)
#pragma unroll
                    for (int s = 0; s < 2; s++)
                        mma16816(c[mt][ng * 2 + s], ah[mt], bh[ng][s], bh[ng][s + 2]);
#pragma unroll
            for (int mt = 0; mt < 2; mt++)
#pragma unroll
                for (int ng = 0; ng < 4; ng++)
#pragma unroll
                    for (int s = 0; s < 2; s++)
                        mma16816(c[mt][ng * 2 + s], ah[mt], bl[ng][s], bl[ng][s + 2]);
#pragma unroll
            for (int mt = 0; mt < 2; mt++)
#pragma unroll
                for (int ng = 0; ng < 4; ng++)
#pragma unroll
                    for (int s = 0; s < 2; s++)
                        mma16816(c[mt][ng * 2 + s], al[mt], bh[ng][s], bh[ng][s + 2]);
        }
    }

    // ---- fused epilogue: v . tanh(C + h) ----
    const int g = lane >> 2, q = lane & 3;
    float* red = (float*)(smem + OFF_RED);
#pragma unroll
    for (int mt = 0; mt < 2; mt++) {
        float r0 = 0.f, r1 = 0.f;
#pragma unroll
        for (int nt = 0; nt < 8; nt++) {
            int n = wn * 64 + nt * 8 + q * 2;
            float v0 = vs[n], v1 = vs[n + 1], h0 = hs[n], h1 = hs[n + 1];
            r0 += v0 * tanh_ffma(c[mt][nt][0] + h0) + v1 * tanh_ffma(c[mt][nt][1] + h1);
            r1 += v0 * tanh_ffma(c[mt][nt][2] + h0) + v1 * tanh_ffma(c[mt][nt][3] + h1);
        }
#pragma unroll
        for (int msk = 1; msk <= 2; msk <<= 1) {
            r0 += __shfl_xor_sync(0xffffffff, r0, msk);
            r1 += __shfl_xor_sync(0xffffffff, r1, msk);
        }
        if (q == 0) {
            int row = wm * 32 + mt * 16 + g;
            red[row * 4 + wn] = r0;
            red[(row + 8) * 4 + wn] = r1;
        }
    }
    __syncthreads();
    if (tid < 128)
        g_partial[(size_t)blockIdx.x * M_TOTAL + m0 + tid] =
            red[tid * 4] + red[tid * 4 + 1] + red[tid * 4 + 2] + red[tid * 4 + 3];
}

// ---------------- kernel 3: softmax ----------------
__global__ void softmax_kernel(float* __restrict__ out) {
    __shared__ float sc[S_];
    __shared__ float rb[256];
    const int b = blockIdx.x, tid = threadIdx.x;
    float lmax = -1e30f;
    for (int s = tid; s < S_; s += 256) {
        float x = g_partial[b * S_ + s] + g_partial[M_TOTAL + b * S_ + s];
        sc[s] = x;
        lmax = fmaxf(lmax, x);
    }
    rb[tid] = lmax; __syncthreads();
    for (int o = 128; o > 0; o >>= 1) {
        if (tid < o) rb[tid] = fmaxf(rb[tid], rb[tid + o]);
        __syncthreads();
    }
    const float m = rb[0]; __syncthreads();
    float ls = 0.f;
    for (int s = tid; s < S_; s += 256) {
        float e = __expf(sc[s] - m);
        sc[s] = e; ls += e;
    }
    rb[tid] = ls; __syncthreads();
    for (int o = 128; o > 0; o >>= 1) {
        if (tid < o) rb[tid] += rb[tid + o];
        __syncthreads();
    }
    const float inv = 1.f / rb[0]; __syncthreads();
    for (int s = tid; s < S_; s += 256)
        out[b * S_ + s] = sc[s] * inv;
}

// ---------------- launcher ----------------
extern "C" void kernel_launch(void* const* d_in, const int* in_sizes, int n_in,
                              void* d_out, int out_size) {
    const float* hidden = (const float*)d_in[0];
    const float* enc    = (const float*)d_in[1];
    const float* W      = (const float*)d_in[2];
    const float* bvec   = (const float*)d_in[3];
    const float* v      = (const float*)d_in[4];
    float* out          = (float*)d_out;

    cudaFuncSetAttribute(gemm_kernel, cudaFuncAttributeMaxDynamicSharedMemorySize, SMEM_DYN);

    conv_we_kernel<<<DEC_, 256>>>(W);
    hproj_kernel<<<dim3(4, B_), 128>>>(hidden, W, bvec);
    gemm_kernel<<<dim3(DEC_ / BN, M_TOTAL / BM), NTHREADS, SMEM_DYN>>>(enc, v);
    softmax_kernel<<<B_, 256>>>(out);
}

// round 16
// speedup vs baseline: 2.5983x; 1.0265x over previous
#include <cuda_runtime.h>
#include <cuda_bf16.h>
#include <cstdint>
#include <math.h>

#define B_      32
#define S_      2048
#define ENC_    1024
#define DEC_    512
#define WROW    1536
#define M_TOTAL 65536

#define BM 128
#define BN 256
#define KC 64
#define NSTAGE 16
#define NTHREADS 512

// smem offsets (from 128-aligned base)
#define OFF_VS    0
#define OFF_HS    1024
#define OFF_AF32  2048                   // 32KB fp32 staging (single buffer; RED aliases it)
#define OFF_ABF0  34816                  // bf16 A: hi 16K + lo 16K
#define OFF_ABF1  67584
#define OFF_BBF0  100352                 // bf16 B: hi 32K + lo 32K
#define OFF_BBF1  165888
#define SMEM_END  231424
#define SMEM_DYN  (SMEM_END + 128)       // 231552

__device__ __align__(256) __nv_bfloat16 g_we_hi[DEC_ * ENC_];
__device__ __align__(256) __nv_bfloat16 g_we_lo[DEC_ * ENC_];
__device__ float g_hproj[B_ * DEC_];
__device__ float g_partial[2 * M_TOTAL];

// ---------------- helpers ----------------
__device__ __forceinline__ uint32_t smem_u32(const void* p) {
    uint32_t a;
    asm("{ .reg .u64 t; cvta.to.shared.u64 t, %1; cvt.u32.u64 %0, t; }" : "=r"(a) : "l"(p));
    return a;
}
__device__ __forceinline__ uint32_t swz(uint32_t o) { return o ^ ((o >> 3) & 0x70); }
__device__ __forceinline__ void cp16(uint32_t dst, const void* src) {
    asm volatile("cp.async.cg.shared.global [%0], [%1], 16;"
                 :: "r"(dst), "l"(__cvta_generic_to_global(src)) : "memory");
}
__device__ __forceinline__ uint32_t pk(__nv_bfloat16 a, __nv_bfloat16 b) {
    __nv_bfloat162 p; p.x = a; p.y = b;
    return *reinterpret_cast<uint32_t*>(&p);
}
__device__ __forceinline__ float tanh_ffma(float x) {
    float xc = fminf(fmaxf(x, -8.f), 8.f);
    float y  = xc * 2.88539008177793f;
    float t  = y + 12582912.f;
    int   k  = __float_as_int(t) - __float_as_int(12582912.f);
    float f  = y - (t - 12582912.f);
    float p = 1.3333558146e-3f;
    p = fmaf(p, f, 9.6181291076e-3f);
    p = fmaf(p, f, 5.5504108664e-2f);
    p = fmaf(p, f, 2.4022650696e-1f);
    p = fmaf(p, f, 6.9314718056e-1f);
    p = fmaf(p, f, 1.0f);
    float E = __int_as_float(__float_as_int(p) + (k << 23));
    float D = E + 1.f;
    float r = __int_as_float(0x7EF311C3 - __float_as_int(D));
    r = r * fmaf(-D, r, 2.f);
    r = r * fmaf(-D, r, 2.f);
    r = r * fmaf(-D, r, 2.f);
    return fmaf(-2.f, r, 1.f);
}
__device__ __forceinline__ void ldsm4(uint32_t* r, uint32_t addr) {
    asm volatile("ldmatrix.sync.aligned.m8n8.x4.shared.b16 {%0,%1,%2,%3}, [%4];"
                 : "=r"(r[0]), "=r"(r[1]), "=r"(r[2]), "=r"(r[3]) : "r"(addr));
}
__device__ __forceinline__ void mma16816(float* c, const uint32_t* a, uint32_t b0, uint32_t b1) {
    asm volatile("mma.sync.aligned.m16n8k16.row.col.f32.bf16.bf16.f32 "
                 "{%0,%1,%2,%3}, {%4,%5,%6,%7}, {%8,%9}, {%0,%1,%2,%3};"
                 : "+f"(c[0]), "+f"(c[1]), "+f"(c[2]), "+f"(c[3])
                 : "r"(a[0]), "r"(a[1]), "r"(a[2]), "r"(a[3]), "r"(b0), "r"(b1));
}

// ---------------- kernel 0: We -> bf16 hi/lo ----------------
__global__ void conv_we_kernel(const float* __restrict__ W) {
    const int d = blockIdx.x, t = threadIdx.x;
    float4 x = *reinterpret_cast<const float4*>(W + (size_t)d * WROW + DEC_ + t * 4);
    float e[4] = {x.x, x.y, x.z, x.w};
    __nv_bfloat16 h[4], l[4];
#pragma unroll
    for (int i = 0; i < 4; i++) {
        h[i] = __float2bfloat16(e[i]);
        l[i] = __float2bfloat16(e[i] - __bfloat162float(h[i]));
    }
    *reinterpret_cast<uint2*>(g_we_hi + d * ENC_ + t * 4) = make_uint2(pk(h[0],h[1]), pk(h[2],h[3]));
    *reinterpret_cast<uint2*>(g_we_lo + d * ENC_ + t * 4) = make_uint2(pk(l[0],l[1]), pk(l[2],l[3]));
}

// ---------------- kernel 1: hproj ----------------
__global__ void hproj_kernel(const float* __restrict__ hidden,
                             const float* __restrict__ W,
                             const float* __restrict__ bvec) {
    __shared__ float hid[DEC_];
    const int b = blockIdx.y;
    const int n = blockIdx.x * 128 + threadIdx.x;
    for (int i = threadIdx.x; i < DEC_; i += 128) hid[i] = hidden[b * DEC_ + i];
    __syncthreads();
    const float4* wr = reinterpret_cast<const float4*>(W + (size_t)n * WROW);
    float acc = bvec[n];
#pragma unroll 8
    for (int k = 0; k < DEC_ / 4; k++) {
        float4 w = wr[k];
        acc += hid[k*4]*w.x + hid[k*4+1]*w.y + hid[k*4+2]*w.z + hid[k*4+3]*w.w;
    }
    g_hproj[b * DEC_ + n] = acc;
}

// ---------------- kernel 2: HMMA GEMM, fused in-loop A conversion ----------------
__global__ __launch_bounds__(NTHREADS, 1)
void gemm_kernel(const float* __restrict__ enc, const float* __restrict__ v) {
    extern __shared__ char sraw[];
    uint32_t sb0 = smem_u32(sraw);
    uint32_t sb = (sb0 + 127u) & ~127u;
    char* smem = sraw + (sb - sb0);

    const int tid  = threadIdx.x;
    const int lane = tid & 31;
    const int w    = tid >> 5;
    const int wm   = w >> 2;
    const int wn   = w & 3;
    const int g8   = lane >> 3;
    const int r8   = lane & 7;
    const int n0   = blockIdx.x * BN;
    const int m0   = blockIdx.y * BM;
    const int batch = m0 >> 11;

    float* vs = (float*)(smem + OFF_VS);
    float* hs = (float*)(smem + OFF_HS);
    if (tid < 256) {
        vs[tid] = v[n0 + tid];
        hs[tid] = g_hproj[batch * DEC_ + n0 + tid];
    }

    // ldsm row-bases + swizzle masks (A lo = hi + 16384, B lo = hi + 32768)
    const int a_row_sel = r8 + (g8 & 1) * 8;
    const uint32_t chunk16 = (uint32_t)((g8 >> 1) * 16);
    uint32_t fA[2], xA[2], fB[4], xB[4];
#pragma unroll
    for (int mt = 0; mt < 2; mt++) {
        uint32_t R = (uint32_t)((wm * 32 + mt * 16 + a_row_sel) * 128);
        fA[mt] = R; xA[mt] = (R >> 3) & 0x70;
    }
#pragma unroll
    for (int ng = 0; ng < 4; ng++) {
        uint32_t R = (uint32_t)((wn * 64 + ng * 16 + a_row_sel) * 128);
        fB[ng] = R; xB[ng] = (R >> 3) & 0x70;
    }

    // per-thread A-fp32 chunk ownership (load AND convert the same bytes)
    int arow[4], acc_[4];
#pragma unroll
    for (int i = 0; i < 4; i++) {
        int id = tid + i * NTHREADS;
        arow[i] = id >> 4;
        acc_[i] = id & 15;
    }

    auto load_af32 = [&](int kb) {
        uint32_t fb = sb + OFF_AF32;
#pragma unroll
        for (int i = 0; i < 4; i++)
            cp16(fb + arow[i] * 256 + acc_[i] * 16,
                 enc + (size_t)(m0 + arow[i]) * ENC_ + kb + acc_[i] * 4);
    };
    auto load_b = [&](uint32_t bb, int kb) {
#pragma unroll
        for (int i = 0; i < 4; i++) {
            int id = tid + i * NTHREADS;
            int row = id >> 3, c = id & 7;
            uint32_t so = swz(row * 128 + c * 16);
            size_t g = (size_t)(n0 + row) * ENC_ + kb + c * 8;
            cp16(bb + so, g_we_hi + g);
            cp16(bb + 32768 + so, g_we_lo + g);
        }
    };
    auto convert_a = [&](uint32_t abf_off) {
        const char* fsrc = smem + OFF_AF32;
        char* adst = smem + abf_off;
#pragma unroll
        for (int i = 0; i < 4; i++) {
            float4 x = *reinterpret_cast<const float4*>(fsrc + arow[i] * 256 + acc_[i] * 16);
            __nv_bfloat16 h0 = __float2bfloat16(x.x), h1 = __float2bfloat16(x.y);
            __nv_bfloat16 h2 = __float2bfloat16(x.z), h3 = __float2bfloat16(x.w);
            __nv_bfloat16 l0 = __float2bfloat16(x.x - __bfloat162float(h0));
            __nv_bfloat16 l1 = __float2bfloat16(x.y - __bfloat162float(h1));
            __nv_bfloat16 l2 = __float2bfloat16(x.z - __bfloat162float(h2));
            __nv_bfloat16 l3 = __float2bfloat16(x.w - __bfloat162float(h3));
            uint32_t so = swz(arow[i] * 128 + acc_[i] * 8);
            *reinterpret_cast<uint2*>(adst + so)         = make_uint2(pk(h0,h1), pk(h2,h3));
            *reinterpret_cast<uint2*>(adst + 16384 + so) = make_uint2(pk(l0,l1), pk(l2,l3));
        }
    };

    // ---- prologue ----
    load_af32(0);
    load_b(sb + OFF_BBF0, 0);
    asm volatile("cp.async.commit_group;" ::: "memory");
    asm volatile("cp.async.wait_group 0;" ::: "memory");
    __syncthreads();
    convert_a(OFF_ABF0);
    load_af32(KC);                       // own chunks only — per-thread safe after convert
    load_b(sb + OFF_BBF1, KC);
    asm volatile("cp.async.commit_group;" ::: "memory");
    __syncthreads();                     // publish ABF0 before stage-0 LDSM

    float c[2][8][4];
#pragma unroll
    for (int mt = 0; mt < 2; mt++)
#pragma unroll
        for (int nt = 0; nt < 8; nt++)
#pragma unroll
            for (int q = 0; q < 4; q++) c[mt][nt][q] = 0.f;

#pragma unroll 1
    for (int kt = 0; kt < NSTAGE; kt++) {
        const int b = kt & 1;
        const uint32_t abf = sb + (b ? OFF_ABF1 : OFF_ABF0);
        const uint32_t bbf = sb + (b ? OFF_BBF1 : OFF_BBF0);

        // compute stage kt: 4 k16 steps, SMSP-rotated, 3 MMA sweeps
#pragma unroll
        for (int kq = 0; kq < 4; kq++) {
            const int k16 = (kq + wm) & 3;
            const uint32_t kk = (uint32_t)(k16 * 32) + chunk16;
            uint32_t ah[2][4], al[2][4], bh[4][4], bl[4][4];
#pragma unroll
            for (int mt = 0; mt < 2; mt++) {
                uint32_t q = abf + fA[mt] + (kk ^ xA[mt]);
                ldsm4(ah[mt], q);
                ldsm4(al[mt], q + 16384);
            }
#pragma unroll
            for (int ng = 0; ng < 4; ng++) {
                uint32_t q = bbf + fB[ng] + (kk ^ xB[ng]);
                ldsm4(bh[ng], q);
                ldsm4(bl[ng], q + 32768);
            }
#pragma unroll
            for (int mt = 0; mt < 2; mt++)
#pragma unroll
                for (int ng = 0; ng < 4; ng++)
#pragma unroll
                    for (int s = 0; s < 2; s++)
                        mma16816(c[mt][ng * 2 + s], ah[mt], bh[ng][s], bh[ng][s + 2]);
#pragma unroll
            for (int mt = 0; mt < 2; mt++)
#pragma unroll
                for (int ng = 0; ng < 4; ng++)
#pragma unroll
                    for (int s = 0; s < 2; s++)
                        mma16816(c[mt][ng * 2 + s], ah[mt], bl[ng][s], bl[ng][s + 2]);
#pragma unroll
            for (int mt = 0; mt < 2; mt++)
#pragma unroll
                for (int ng = 0; ng < 4; ng++)
#pragma unroll
                    for (int s = 0; s < 2; s++)
                        mma16816(c[mt][ng * 2 + s], al[mt], bh[ng][s], bh[ng][s + 2]);
        }

        // stage tail
        if (kt + 1 < NSTAGE) {
            asm volatile("cp.async.wait_group 0;" ::: "memory");
            __syncthreads();                         // sync1: BBF(b)/ABF(nb) readers done
            convert_a((kt + 1) & 1 ? OFF_ABF1 : OFF_ABF0);
            if (kt + 2 < NSTAGE) {
                load_af32((kt + 2) * KC);
                load_b(bbf, (kt + 2) * KC);          // reuse BBF(b), drained past sync1
                asm volatile("cp.async.commit_group;" ::: "memory");
            }
            __syncthreads();                         // sync2: publish ABF(kt+1)
        }
    }

    // ---- fused epilogue: v . tanh(C + h) ----
    __syncthreads();
    const int g = lane >> 2, q = lane & 3;
    float* red = (float*)(smem + OFF_AF32);
#pragma unroll
    for (int mt = 0; mt < 2; mt++) {
        float r0 = 0.f, r1 = 0.f;
#pragma unroll
        for (int nt = 0; nt < 8; nt++) {
            int n = wn * 64 + nt * 8 + q * 2;
            float v0 = vs[n], v1 = vs[n + 1], h0 = hs[n], h1 = hs[n + 1];
            r0 += v0 * tanh_ffma(c[mt][nt][0] + h0) + v1 * tanh_ffma(c[mt][nt][1] + h1);
            r1 += v0 * tanh_ffma(c[mt][nt][2] + h0) + v1 * tanh_ffma(c[mt][nt][3] + h1);
        }
#pragma unroll
        for (int msk = 1; msk <= 2; msk <<= 1) {
            r0 += __shfl_xor_sync(0xffffffff, r0, msk);
            r1 += __shfl_xor_sync(0xffffffff, r1, msk);
        }
        if (q == 0) {
            int row = wm * 32 + mt * 16 + g;
            red[row * 4 + wn] = r0;
            red[(row + 8) * 4 + wn] = r1;
        }
    }
    __syncthreads();
    if (tid < 128)
        g_partial[(size_t)blockIdx.x * M_TOTAL + m0 + tid] =
            red[tid * 4] + red[tid * 4 + 1] + red[tid * 4 + 2] + red[tid * 4 + 3];
}

// ---------------- kernel 3: softmax ----------------
__global__ void softmax_kernel(float* __restrict__ out) {
    __shared__ float sc[S_];
    __shared__ float rb[256];
    const int b = blockIdx.x, tid = threadIdx.x;
    float lmax = -1e30f;
    for (int s = tid; s < S_; s += 256) {
        float x = g_partial[b * S_ + s] + g_partial[M_TOTAL + b * S_ + s];
        sc[s] = x;
        lmax = fmaxf(lmax, x);
    }
    rb[tid] = lmax; __syncthreads();
    for (int o = 128; o > 0; o >>= 1) {
        if (tid < o) rb[tid] = fmaxf(rb[tid], rb[tid + o]);
        __syncthreads();
    }
    const float m = rb[0]; __syncthreads();
    float ls = 0.f;
    for (int s = tid; s < S_; s += 256) {
        float e = __expf(sc[s] - m);
        sc[s] = e; ls += e;
    }
    rb[tid] = ls; __syncthreads();
    for (int o = 128; o > 0; o >>= 1) {
        if (tid < o) rb[tid] += rb[tid + o];
        __syncthreads();
    }
    const float inv = 1.f / rb[0]; __syncthreads();
    for (int s = tid; s < S_; s += 256)
        out[b * S_ + s] = sc[s] * inv;
}

// ---------------- launcher ----------------
extern "C" void kernel_launch(void* const* d_in, const int* in_sizes, int n_in,
                              void* d_out, int out_size) {
    const float* hidden = (const float*)d_in[0];
    const float* enc    = (const float*)d_in[1];
    const float* W      = (const float*)d_in[2];
    const float* bvec   = (const float*)d_in[3];
    const float* v      = (const float*)d_in[4];
    float* out          = (float*)d_out;

    cudaFuncSetAttribute(gemm_kernel, cudaFuncAttributeMaxDynamicSharedMemorySize, SMEM_DYN);

    conv_we_kernel<<<DEC_, 256>>>(W);
    hproj_kernel<<<dim3(4, B_), 128>>>(hidden, W, bvec);
    gemm_kernel<<<dim3(DEC_ / BN, M_TOTAL / BM), NTHREADS, SMEM_DYN>>>(enc, v);
    softmax_kernel<<<B_, 256>>>(out);
}